// round 1
// baseline (speedup 1.0000x reference)
#include <cuda_runtime.h>

#define NB 1024
#define NN 64
#define DD 128
#define NE 512
#define BE (NB*NE)
#define HS 129                 // padded smem row stride (conflict-free)
#define HSZ (NN*HS)            // 8256 floats
#define SIMS_S 65
#define P1C (32*33)
#define FEAT_DIM 12288

// static device scratch (allocation-free rule)
__device__ float g_feat[NB*FEAT_DIM];
__device__ float g_hid[NB*512];

// smem layout (floats):
//   Hq[HSZ] Hc[HSZ] Mq[HSZ] Mc[HSZ]   (M region reused as sims/p1/w2s during conv)
//   tail: csr + dis + conv1 weights
#define SMEM_WORDS (4*HSZ + 2762)
#define SMEM_BYTES (SMEM_WORDS*4)

__global__ __launch_bounds__(512, 1)
void fused_kernel(const float* __restrict__ x_q, const float* __restrict__ x_c,
                  const float* __restrict__ w0, const float* __restrict__ b0,
                  const float* __restrict__ w1, const float* __restrict__ b1,
                  const float* __restrict__ w2, const float* __restrict__ b2,
                  const float* __restrict__ c1w, const float* __restrict__ c1b,
                  const float* __restrict__ c2w, const float* __restrict__ c2b,
                  const int* __restrict__ eiq, const int* __restrict__ eic)
{
    extern __shared__ float sm[];
    float* Hq = sm;
    float* Hc = Hq + HSZ;
    float* Mq = Hc + HSZ;
    float* Mc = Mq + HSZ;
    // conv-phase aliases of the M region (GEMM M tiles dead by then)
    float* sims = Mq;                 // 64*65 = 4160
    float* p1   = Mq + 4160;          // 8*32*33 = 8448
    float* w2s  = Mq + 4160 + 8448;   // 3200  (total 15808 <= 16512)
    float* tail = sm + 4*HSZ;
    int*   off_q = (int*)tail;        // 65
    int*   off_c = off_q + 65;        // 65
    int*   cntq  = off_c + 65;        // 64
    int*   cntc  = cntq + 64;         // 64
    int*   curq  = cntc + 64;         // 64
    int*   curc  = curq + 64;         // 64
    int*   csq   = curc + 64;         // 512
    int*   csc   = csq + 512;         // 512
    float* cnq   = (float*)(csc + 512); // 512
    float* cnc   = cnq + 512;         // 512
    float* disq  = cnc + 512;         // 64
    float* disc  = disq + 64;         // 64
    float* w1s   = disc + 64;         // 200

    const int b    = blockIdx.x;
    const int t    = threadIdx.x;
    const int base = b * NN;

    // ---- load node features (both graphs) ----
    for (int idx = t; idx < NN*DD; idx += 512) {
        int i = idx >> 7, k = idx & 127;
        Hq[i*HS + k] = x_q[(base + i)*DD + k];
        Hc[i*HS + k] = x_c[(base + i)*DD + k];
    }
    if (t < 64) { cntq[t] = 0; cntc[t] = 0; }
    __syncthreads();

    // ---- edges: count degrees, stage packed (s,d) in (dead) M region ----
    int* tq = (int*)Mq;
    int* tc = (int*)Mc;
    if (t < NE) {
        int e = b*NE + t;
        int s = eiq[e] - base, d = eiq[BE + e] - base;
        tq[t] = (s << 8) | d;
        atomicAdd(&cntq[d], 1);
        s = eic[e] - base; d = eic[BE + e] - base;
        tc[t] = (s << 8) | d;
        atomicAdd(&cntc[d], 1);
    }
    __syncthreads();
    if (t < 64)        disq[t]      = rsqrtf((float)cntq[t] + 1.0f);
    else if (t < 128)  disc[t - 64] = rsqrtf((float)cntc[t - 64] + 1.0f);
    if (t == 0)  { int a = 0; for (int i = 0; i < 64; i++){ off_q[i] = a; a += cntq[i]; } off_q[64] = a; }
    if (t == 32) { int a = 0; for (int i = 0; i < 64; i++){ off_c[i] = a; a += cntc[i]; } off_c[64] = a; }
    __syncthreads();
    if (t < 64) { curq[t] = off_q[t]; curc[t] = off_c[t]; }
    __syncthreads();
    if (t < NE) {
        int sd = tq[t]; int s = sd >> 8, d = sd & 255;
        int p = atomicAdd(&curq[d], 1);
        csq[p] = s; cnq[p] = disq[s] * disq[d];
        sd = tc[t]; s = sd >> 8; d = sd & 255;
        p = atomicAdd(&curc[d], 1);
        csc[p] = s; cnc[p] = disc[s] * disc[d];
    }
    __syncthreads();

    const int tx = t & 31, ty = t >> 5;   // GEMM mapping: 32 j-groups x 16 i-groups

    for (int l = 0; l < 3; l++) {
        const float* W  = (l == 0) ? w0 : (l == 1) ? w1 : w2;
        const float* bb = (l == 0) ? b0 : (l == 1) ? b1 : b2;

        // ---- GEMM: M = (relu?)(H) @ W, both graphs, 4x4 micro-tiles ----
        {
            const int j0 = tx * 4, i0 = ty * 4;
            float aq[4][4] = {}, ac[4][4] = {};
            for (int k = 0; k < DD; k++) {
                float4 wv = *reinterpret_cast<const float4*>(W + k*DD + j0);
                #pragma unroll
                for (int r = 0; r < 4; r++) {
                    float hq = Hq[(i0 + r)*HS + k];
                    float hc = Hc[(i0 + r)*HS + k];
                    if (l) { hq = fmaxf(hq, 0.f); hc = fmaxf(hc, 0.f); }
                    aq[r][0] += hq*wv.x; aq[r][1] += hq*wv.y; aq[r][2] += hq*wv.z; aq[r][3] += hq*wv.w;
                    ac[r][0] += hc*wv.x; ac[r][1] += hc*wv.y; ac[r][2] += hc*wv.z; ac[r][3] += hc*wv.w;
                }
            }
            #pragma unroll
            for (int r = 0; r < 4; r++)
                #pragma unroll
                for (int c = 0; c < 4; c++) {
                    Mq[(i0 + r)*HS + j0 + c] = aq[r][c];
                    Mc[(i0 + r)*HS + j0 + c] = ac[r][c];
                }
        }
        __syncthreads();

        // ---- aggregate via CSR: out = b + dis^2*M[i] + sum M[src]*norm ; write into H ----
        {
            const int f = t & 127, g = t >> 7;   // g in 0..3
            float bf = bb[f];
            #pragma unroll 1
            for (int r = 0; r < 16; r++) {
                int i = g + (r << 2);
                float acc = bf + disq[i]*disq[i]*Mq[i*HS + f];
                int e0 = off_q[i], e1 = off_q[i + 1];
                for (int p = e0; p < e1; p++) acc += Mq[csq[p]*HS + f] * cnq[p];
                Hq[i*HS + f] = acc;
                acc = bf + disc[i]*disc[i]*Mc[i*HS + f];
                e0 = off_c[i]; e1 = off_c[i + 1];
                for (int p = e0; p < e1; p++) acc += Mc[csc[p]*HS + f] * cnc[p];
                Hc[i*HS + f] = acc;
            }
        }
        __syncthreads();

        // ---- sims = out_q @ out_c^T  (pre-relu feats) ----
        {
            const int j = t & 63, i0s = t >> 6;  // 0..7
            float acc[8] = {};
            for (int k = 0; k < DD; k++) {
                float cv = Hc[j*HS + k];
                #pragma unroll
                for (int r = 0; r < 8; r++) acc[r] += Hq[(i0s + (r << 3))*HS + k] * cv;
            }
            #pragma unroll
            for (int r = 0; r < 8; r++) sims[(i0s + (r << 3))*SIMS_S + j] = acc[r];
        }
        // stage conv weights for this layer (disjoint smem regions)
        for (int idx = t; idx < 200;  idx += 512) w1s[idx] = c1w[l*200  + idx];
        for (int idx = t; idx < 3200; idx += 512) w2s[idx] = c2w[l*3200 + idx];
        __syncthreads();

        // ---- conv1 (1->8, 5x5, pad2) + relu + 2x2 maxpool -> p1[8][32][32] ----
        {
            const int x = t & 31, g5 = t >> 5;  // 0..15
            #pragma unroll 1
            for (int r = 0; r < 16; r++) {
                int idx = g5 + (r << 4);        // 0..255
                int c = idx >> 5, y = idx & 31;
                float b1v = c1b[l*8 + c];
                float v00 = b1v, v01 = b1v, v10 = b1v, v11 = b1v;
                int Y = 2*y, X = 2*x;
                #pragma unroll
                for (int dy = 0; dy < 5; dy++) {
                    int iy = Y + dy - 2;
                    bool oky0 = (unsigned)iy < 64u;
                    bool oky1 = (unsigned)(iy + 1) < 64u;
                    #pragma unroll
                    for (int dx = 0; dx < 5; dx++) {
                        float w = w1s[c*25 + dy*5 + dx];
                        int ix = X + dx - 2;
                        bool okx0 = (unsigned)ix < 64u;
                        bool okx1 = (unsigned)(ix + 1) < 64u;
                        float s00 = (oky0 && okx0) ? sims[iy*SIMS_S + ix]       : 0.f;
                        float s01 = (oky0 && okx1) ? sims[iy*SIMS_S + ix + 1]   : 0.f;
                        float s10 = (oky1 && okx0) ? sims[(iy+1)*SIMS_S + ix]   : 0.f;
                        float s11 = (oky1 && okx1) ? sims[(iy+1)*SIMS_S + ix+1] : 0.f;
                        v00 += s00*w; v01 += s01*w; v10 += s10*w; v11 += s11*w;
                    }
                }
                float mx = fmaxf(fmaxf(v00, v01), fmaxf(v10, v11));
                p1[c*P1C + y*33 + x] = fmaxf(mx, 0.f);
            }
        }
        __syncthreads();

        // ---- conv2 (8->16, 5x5, pad2) + relu + 2x2 maxpool -> feat (global) ----
        {
            const int x = t & 15, g4 = t >> 4;  // 0..31
            #pragma unroll 1
            for (int r = 0; r < 8; r++) {
                int idx = g4 + (r << 5);        // 0..255
                int c = idx >> 4, y = idx & 15;
                float b2v = c2b[l*16 + c];
                float v00 = b2v, v01 = b2v, v10 = b2v, v11 = b2v;
                int Y = 2*y, X = 2*x;
                const float* wc = w2s + c*200;
                #pragma unroll 1
                for (int ci = 0; ci < 8; ci++) {
                    const float* pp  = p1 + ci*P1C;
                    const float* wci = wc + ci*25;
                    #pragma unroll
                    for (int dy = 0; dy < 5; dy++) {
                        int iy = Y + dy - 2;
                        bool oky0 = (unsigned)iy < 32u;
                        bool oky1 = (unsigned)(iy + 1) < 32u;
                        #pragma unroll
                        for (int dx = 0; dx < 5; dx++) {
                            float w = wci[dy*5 + dx];
                            int ix = X + dx - 2;
                            bool okx0 = (unsigned)ix < 32u;
                            bool okx1 = (unsigned)(ix + 1) < 32u;
                            float s00 = (oky0 && okx0) ? pp[iy*33 + ix]       : 0.f;
                            float s01 = (oky0 && okx1) ? pp[iy*33 + ix + 1]   : 0.f;
                            float s10 = (oky1 && okx0) ? pp[(iy+1)*33 + ix]   : 0.f;
                            float s11 = (oky1 && okx1) ? pp[(iy+1)*33 + ix+1] : 0.f;
                            v00 += s00*w; v01 += s01*w; v10 += s10*w; v11 += s11*w;
                        }
                    }
                }
                float mx = fmaxf(fmaxf(v00, v01), fmaxf(v10, v11));
                g_feat[b*FEAT_DIM + ((l*16 + c)*16 + y)*16 + x] = fmaxf(mx, 0.f);
            }
        }
        __syncthreads();
    }
}

// ---- h = relu(feat @ lin_w + lin_b) :  1024x12288 @ 12288x512 ----
__global__ __launch_bounds__(256)
void lin_kernel(const float* __restrict__ Wl, const float* __restrict__ bl)
{
    __shared__ float As[64][33];
    __shared__ float Bs[32][64];
    const int bn = blockIdx.x & 7;    // 8 N tiles of 64
    const int bm = blockIdx.x >> 3;   // 16 M tiles of 64
    const int t  = threadIdx.x;
    const int txg = t & 15, tyg = t >> 4;
    const int j0 = txg * 4, i0 = tyg * 4;
    const int rowBase = bm * 64, colBase = bn * 64;
    float acc[4][4] = {};
    for (int kt = 0; kt < FEAT_DIM; kt += 32) {
        #pragma unroll
        for (int r = 0; r < 8; r++) {
            int idx = t + r*256;
            int row = idx >> 5, kk = idx & 31;
            As[row][kk] = g_feat[(rowBase + row)*FEAT_DIM + kt + kk];
        }
        #pragma unroll
        for (int r = 0; r < 8; r++) {
            int idx = t + r*256;
            int row = idx >> 6, col = idx & 63;
            Bs[row][col] = Wl[(kt + row)*512 + colBase + col];
        }
        __syncthreads();
        #pragma unroll
        for (int k = 0; k < 32; k++) {
            float4 bv = *reinterpret_cast<const float4*>(&Bs[k][j0]);
            #pragma unroll
            for (int r = 0; r < 4; r++) {
                float a = As[i0 + r][k];
                acc[r][0] += a*bv.x; acc[r][1] += a*bv.y; acc[r][2] += a*bv.z; acc[r][3] += a*bv.w;
            }
        }
        __syncthreads();
    }
    #pragma unroll
    for (int r = 0; r < 4; r++)
        #pragma unroll
        for (int c = 0; c < 4; c++)
            g_hid[(rowBase + i0 + r)*512 + colBase + j0 + c] =
                fmaxf(acc[r][c] + bl[colBase + j0 + c], 0.f);
}

// ---- out = h @ score_w + score_b : one warp per row ----
__global__ __launch_bounds__(256)
void score_kernel(const float* __restrict__ sw, const float* __restrict__ sb,
                  float* __restrict__ out)
{
    int gw   = (blockIdx.x * blockDim.x + threadIdx.x) >> 5;
    int lane = threadIdx.x & 31;
    if (gw >= NB) return;
    const float* h = g_hid + gw * 512;
    float s = 0.f;
    #pragma unroll
    for (int j = lane; j < 512; j += 32) s += h[j] * sw[j];
    #pragma unroll
    for (int o = 16; o > 0; o >>= 1) s += __shfl_xor_sync(0xFFFFFFFFu, s, o);
    if (lane == 0) out[gw] = s + sb[0];
}

extern "C" void kernel_launch(void* const* d_in, const int* in_sizes, int n_in,
                              void* d_out, int out_size)
{
    const float* x_q  = (const float*)d_in[0];
    const float* x_c  = (const float*)d_in[1];
    const float* w0   = (const float*)d_in[2];
    const float* b0   = (const float*)d_in[3];
    const float* w1   = (const float*)d_in[4];
    const float* b1   = (const float*)d_in[5];
    const float* w2   = (const float*)d_in[6];
    const float* b2   = (const float*)d_in[7];
    const float* c1w  = (const float*)d_in[8];
    const float* c1b  = (const float*)d_in[9];
    const float* c2w  = (const float*)d_in[10];
    const float* c2b  = (const float*)d_in[11];
    const float* linw = (const float*)d_in[12];
    const float* linb = (const float*)d_in[13];
    const float* scw  = (const float*)d_in[14];
    const float* scb  = (const float*)d_in[15];
    const int*   eiq  = (const int*)d_in[16];
    const int*   eic  = (const int*)d_in[17];

    cudaFuncSetAttribute(fused_kernel, cudaFuncAttributeMaxDynamicSharedMemorySize, SMEM_BYTES);

    fused_kernel<<<NB, 512, SMEM_BYTES>>>(x_q, x_c, w0, b0, w1, b1, w2, b2,
                                          c1w, c1b, c2w, c2b, eiq, eic);
    lin_kernel<<<128, 256>>>(linw, linb);
    score_kernel<<<128, 256>>>(scw, scb, (float*)d_out);
}

// round 3
// speedup vs baseline: 1.8311x; 1.8311x over previous
#include <cuda_runtime.h>

#define NB 1024
#define NN 64
#define DD 128
#define NE 512
#define BE (NB*NE)
#define HS 132                 // padded smem row stride (float4-aligned)
#define HSZ (NN*HS)            // 8448 floats
#define SIMS_S 72              // 4 pad | 64 data | 4 pad
#define P1S 40                 // 4 pad | 32 data | 4 pad
#define FEAT_DIM 12288

// static device scratch (allocation-free rule)
__device__ float g_feat[NB*FEAT_DIM];
__device__ float g_hid[NB*512];

// smem: Hq[HSZ] Hc[HSZ] Mq[HSZ] Mc[HSZ] tail
#define TAIL_WORDS 5962
#define SMEM_WORDS (4*HSZ + TAIL_WORDS)
#define SMEM_BYTES (SMEM_WORDS*4)

__device__ __forceinline__ float relu(float v) { return fmaxf(v, 0.f); }

__global__ __launch_bounds__(512, 1)
void fused_kernel(const float* __restrict__ x_q, const float* __restrict__ x_c,
                  const float* __restrict__ w0, const float* __restrict__ b0,
                  const float* __restrict__ w1, const float* __restrict__ b1,
                  const float* __restrict__ w2, const float* __restrict__ b2,
                  const float* __restrict__ c1w, const float* __restrict__ c1b,
                  const float* __restrict__ c2w, const float* __restrict__ c2b,
                  const int* __restrict__ eiq, const int* __restrict__ eic)
{
    extern __shared__ float sm[];
    float* Hq = sm;
    float* Hc = Hq + HSZ;
    float* Mq = Hc + HSZ;
    float* Mc = Mq + HSZ;
    // conv-phase aliases of the M region (GEMM outputs dead by then)
    float* sims = Mq;                 // 64*72 = 4608
    float* p1   = Mq + 4608;          // 8*32*40 = 10240
    float* tail = sm + 4*HSZ;
    int*   off_q = (int*)tail;        // 65
    int*   off_c = off_q + 65;        // 65
    int*   cntq  = off_c + 65;        // 64
    int*   cntc  = cntq + 64;         // 64
    int*   curq  = cntc + 64;         // 64
    int*   curc  = curq + 64;         // 64
    int*   csq   = curc + 64;         // 512
    int*   csc   = csq + 512;         // 512
    float* cnq   = (float*)(csc + 512); // 512
    float* cnc   = cnq + 512;         // 512
    float* disq  = cnc + 512;         // 64
    float* disc  = disq + 64;         // 64
    float* w1s   = disc + 64;         // 200
    float* w2s   = w1s + 200;         // 3200

    const int b    = blockIdx.x;
    const int t    = threadIdx.x;
    const int base = b * NN;

    // ---- load node features (both graphs), vectorized ----
    for (int idx = t; idx < NN*DD/4; idx += 512) {
        int i = idx >> 5, k4 = (idx & 31) * 4;
        *reinterpret_cast<float4*>(&Hq[i*HS + k4]) =
            *reinterpret_cast<const float4*>(&x_q[(base + i)*DD + k4]);
        *reinterpret_cast<float4*>(&Hc[i*HS + k4]) =
            *reinterpret_cast<const float4*>(&x_c[(base + i)*DD + k4]);
    }
    if (t < 64) { cntq[t] = 0; cntc[t] = 0; }
    __syncthreads();

    // ---- edges: degree count; stage packed (s,d) in (dead) M region ----
    int* tq = (int*)Mq;
    int* tc = (int*)Mc;
    if (t < NE) {
        int e = b*NE + t;
        int s = eiq[e] - base, d = eiq[BE + e] - base;
        tq[t] = (s << 8) | d;
        atomicAdd(&cntq[d], 1);
        s = eic[e] - base; d = eic[BE + e] - base;
        tc[t] = (s << 8) | d;
        atomicAdd(&cntc[d], 1);
    }
    __syncthreads();
    if (t < 64)        disq[t]      = rsqrtf((float)cntq[t] + 1.0f);
    else if (t < 128)  disc[t - 64] = rsqrtf((float)cntc[t - 64] + 1.0f);
    if (t == 0)  { int a = 0; for (int i = 0; i < 64; i++){ off_q[i] = a; a += cntq[i]; } off_q[64] = a; }
    if (t == 32) { int a = 0; for (int i = 0; i < 64; i++){ off_c[i] = a; a += cntc[i]; } off_c[64] = a; }
    __syncthreads();
    if (t < 64) { curq[t] = off_q[t]; curc[t] = off_c[t]; }
    __syncthreads();
    if (t < NE) {
        int sd = tq[t]; int s = sd >> 8, d = sd & 255;
        int p = atomicAdd(&curq[d], 1);
        csq[p] = s; cnq[p] = disq[s] * disq[d];
        sd = tc[t]; s = sd >> 8; d = sd & 255;
        p = atomicAdd(&curc[d], 1);
        csc[p] = s; cnc[p] = disc[s] * disc[d];
    }
    __syncthreads();

    for (int l = 0; l < 3; l++) {
        const float* W  = (l == 0) ? w0 : (l == 1) ? w1 : w2;
        const float* bb = (l == 0) ? b0 : (l == 1) ? b1 : b2;

        // ---- GEMM: M = (relu?)(H) @ W, both graphs, 4x4 micro-tiles, float4 k ----
        {
            const int j0 = (t & 31) * 4, i0 = (t >> 5) * 4;
            float4 aq[4], ac[4];
            #pragma unroll
            for (int r = 0; r < 4; r++) { aq[r] = make_float4(0,0,0,0); ac[r] = make_float4(0,0,0,0); }
            for (int k = 0; k < DD; k += 4) {
                float4 hq[4], hc[4];
                #pragma unroll
                for (int r = 0; r < 4; r++) {
                    hq[r] = *reinterpret_cast<const float4*>(&Hq[(i0 + r)*HS + k]);
                    hc[r] = *reinterpret_cast<const float4*>(&Hc[(i0 + r)*HS + k]);
                    if (l) {
                        hq[r].x = relu(hq[r].x); hq[r].y = relu(hq[r].y);
                        hq[r].z = relu(hq[r].z); hq[r].w = relu(hq[r].w);
                        hc[r].x = relu(hc[r].x); hc[r].y = relu(hc[r].y);
                        hc[r].z = relu(hc[r].z); hc[r].w = relu(hc[r].w);
                    }
                }
                #pragma unroll
                for (int kk = 0; kk < 4; kk++) {
                    float4 wv = *reinterpret_cast<const float4*>(W + (k + kk)*DD + j0);
                    #pragma unroll
                    for (int r = 0; r < 4; r++) {
                        float a = kk == 0 ? hq[r].x : kk == 1 ? hq[r].y : kk == 2 ? hq[r].z : hq[r].w;
                        aq[r].x += a*wv.x; aq[r].y += a*wv.y; aq[r].z += a*wv.z; aq[r].w += a*wv.w;
                        float c = kk == 0 ? hc[r].x : kk == 1 ? hc[r].y : kk == 2 ? hc[r].z : hc[r].w;
                        ac[r].x += c*wv.x; ac[r].y += c*wv.y; ac[r].z += c*wv.z; ac[r].w += c*wv.w;
                    }
                }
            }
            #pragma unroll
            for (int r = 0; r < 4; r++) {
                *reinterpret_cast<float4*>(&Mq[(i0 + r)*HS + j0]) = aq[r];
                *reinterpret_cast<float4*>(&Mc[(i0 + r)*HS + j0]) = ac[r];
            }
        }
        __syncthreads();

        // ---- aggregate via CSR: out = b + dis^2*M[i] + sum M[src]*norm ; into H ----
        {
            const int f = t & 127, g = t >> 7;   // g in 0..3
            float bf = bb[f];
            #pragma unroll 1
            for (int r = 0; r < 16; r++) {
                int i = g + (r << 2);
                float acc = bf + disq[i]*disq[i]*Mq[i*HS + f];
                int e0 = off_q[i], e1 = off_q[i + 1];
                for (int p = e0; p < e1; p++) acc += Mq[csq[p]*HS + f] * cnq[p];
                Hq[i*HS + f] = acc;
                acc = bf + disc[i]*disc[i]*Mc[i*HS + f];
                e0 = off_c[i]; e1 = off_c[i + 1];
                for (int p = e0; p < e1; p++) acc += Mc[csc[p]*HS + f] * cnc[p];
                Hc[i*HS + f] = acc;
            }
        }
        __syncthreads();

        // ---- sims = out_q @ out_c^T (pre-relu), 4i x {j, j+32}, float4 k ----
        {
            const int j = t & 31, ig = t >> 5;   // i0 = ig*4
            float acc[4][2] = {};
            for (int k = 0; k < DD; k += 4) {
                float4 ca = *reinterpret_cast<const float4*>(&Hc[j*HS + k]);
                float4 cb = *reinterpret_cast<const float4*>(&Hc[(j + 32)*HS + k]);
                #pragma unroll
                for (int r = 0; r < 4; r++) {
                    float4 qv = *reinterpret_cast<const float4*>(&Hq[(ig*4 + r)*HS + k]);
                    acc[r][0] += qv.x*ca.x; acc[r][0] += qv.y*ca.y;
                    acc[r][0] += qv.z*ca.z; acc[r][0] += qv.w*ca.w;
                    acc[r][1] += qv.x*cb.x; acc[r][1] += qv.y*cb.y;
                    acc[r][1] += qv.z*cb.z; acc[r][1] += qv.w*cb.w;
                }
            }
            #pragma unroll
            for (int r = 0; r < 4; r++) {
                sims[(ig*4 + r)*SIMS_S + 4 + j]      = acc[r][0];
                sims[(ig*4 + r)*SIMS_S + 4 + j + 32] = acc[r][1];
            }
        }
        // zero the column pads of sims (64 rows x 8) and p1 (256 rows x 8)
        for (int idx = t; idx < 2560; idx += 512) {
            if (idx < 512) {
                int row = idx >> 3, pc = idx & 7;
                sims[row*SIMS_S + (pc < 4 ? pc : pc + 64)] = 0.f;   // FIXED: right pad 68..71
            } else {
                int k2 = idx - 512;
                int row = k2 >> 3, pc = k2 & 7;
                p1[row*P1S + (pc < 4 ? pc : pc + 32)] = 0.f;
            }
        }
        // stage conv weights for this layer
        for (int idx = t; idx < 200;  idx += 512) w1s[idx] = c1w[l*200  + idx];
        for (int idx = t; idx < 3200; idx += 512) w2s[idx] = c2w[l*3200 + idx];
        __syncthreads();

        // ---- conv1 (1->8,5x5,pad2)+relu+pool2 -> p1[8][32][32(+pad)] ----
        #pragma unroll 1
        for (int it = 0; it < 4; it++) {
            int item = it*512 + t;
            int xg = item & 7, py = (item >> 3) & 31, c = item >> 8;
            int Xc = xg * 8, Y = py * 2;
            float w[25];
            #pragma unroll
            for (int i = 0; i < 25; i++) w[i] = w1s[c*25 + i];
            float bias = c1b[l*8 + c];
            float a0[8], a1[8];
            #pragma unroll
            for (int j = 0; j < 8; j++) { a0[j] = bias; a1[j] = bias; }
            #pragma unroll
            for (int iy6 = 0; iy6 < 6; iy6++) {
                int iy = Y - 2 + iy6;
                float in[16];
                if ((unsigned)iy < 64u) {
                    const float* rp = &sims[iy*SIMS_S + Xc];
                    float4 v0 = *reinterpret_cast<const float4*>(rp);
                    float4 v1 = *reinterpret_cast<const float4*>(rp + 4);
                    float4 v2 = *reinterpret_cast<const float4*>(rp + 8);
                    float4 v3 = *reinterpret_cast<const float4*>(rp + 12);
                    in[0]=v0.x; in[1]=v0.y; in[2]=v0.z; in[3]=v0.w;
                    in[4]=v1.x; in[5]=v1.y; in[6]=v1.z; in[7]=v1.w;
                    in[8]=v2.x; in[9]=v2.y; in[10]=v2.z; in[11]=v2.w;
                    in[12]=v3.x; in[13]=v3.y; in[14]=v3.z; in[15]=v3.w;
                } else {
                    #pragma unroll
                    for (int i = 0; i < 16; i++) in[i] = 0.f;
                }
                if (iy6 < 5) {
                    #pragma unroll
                    for (int dx = 0; dx < 5; dx++) {
                        float wv = w[iy6*5 + dx];
                        #pragma unroll
                        for (int j = 0; j < 8; j++) a0[j] += in[j + dx + 2] * wv;
                    }
                }
                if (iy6 >= 1) {
                    #pragma unroll
                    for (int dx = 0; dx < 5; dx++) {
                        float wv = w[(iy6 - 1)*5 + dx];
                        #pragma unroll
                        for (int j = 0; j < 8; j++) a1[j] += in[j + dx + 2] * wv;
                    }
                }
            }
            float4 o;
            o.x = relu(fmaxf(fmaxf(a0[0], a0[1]), fmaxf(a1[0], a1[1])));
            o.y = relu(fmaxf(fmaxf(a0[2], a0[3]), fmaxf(a1[2], a1[3])));
            o.z = relu(fmaxf(fmaxf(a0[4], a0[5]), fmaxf(a1[4], a1[5])));
            o.w = relu(fmaxf(fmaxf(a0[6], a0[7]), fmaxf(a1[6], a1[7])));
            *reinterpret_cast<float4*>(&p1[(c*32 + py)*P1S + 4 + xg*4]) = o;
        }
        __syncthreads();

        // ---- conv2 (8->16,5x5,pad2)+relu+pool2 -> g_feat ----
        #pragma unroll 1
        for (int it = 0; it < 2; it++) {
            int item = it*512 + t;
            int xg = item & 3, py = (item >> 2) & 15, c = item >> 6;
            int Xc = xg * 8, Y = py * 2;
            float bias = c2b[l*16 + c];
            float a0[8], a1[8];
            #pragma unroll
            for (int j = 0; j < 8; j++) { a0[j] = bias; a1[j] = bias; }
            #pragma unroll 1
            for (int ci = 0; ci < 8; ci++) {
                float w[25];
                #pragma unroll
                for (int i = 0; i < 25; i++) w[i] = w2s[(c*8 + ci)*25 + i];
                const float* pch = p1 + ci*32*P1S;
                #pragma unroll
                for (int iy6 = 0; iy6 < 6; iy6++) {
                    int iy = Y - 2 + iy6;
                    float in[16];
                    if ((unsigned)iy < 32u) {
                        const float* rp = pch + iy*P1S + Xc;
                        float4 v0 = *reinterpret_cast<const float4*>(rp);
                        float4 v1 = *reinterpret_cast<const float4*>(rp + 4);
                        float4 v2 = *reinterpret_cast<const float4*>(rp + 8);
                        float4 v3 = *reinterpret_cast<const float4*>(rp + 12);
                        in[0]=v0.x; in[1]=v0.y; in[2]=v0.z; in[3]=v0.w;
                        in[4]=v1.x; in[5]=v1.y; in[6]=v1.z; in[7]=v1.w;
                        in[8]=v2.x; in[9]=v2.y; in[10]=v2.z; in[11]=v2.w;
                        in[12]=v3.x; in[13]=v3.y; in[14]=v3.z; in[15]=v3.w;
                    } else {
                        #pragma unroll
                        for (int i = 0; i < 16; i++) in[i] = 0.f;
                    }
                    if (iy6 < 5) {
                        #pragma unroll
                        for (int dx = 0; dx < 5; dx++) {
                            float wv = w[iy6*5 + dx];
                            #pragma unroll
                            for (int j = 0; j < 8; j++) a0[j] += in[j + dx + 2] * wv;
                        }
                    }
                    if (iy6 >= 1) {
                        #pragma unroll
                        for (int dx = 0; dx < 5; dx++) {
                            float wv = w[(iy6 - 1)*5 + dx];
                            #pragma unroll
                            for (int j = 0; j < 8; j++) a1[j] += in[j + dx + 2] * wv;
                        }
                    }
                }
            }
            float4 o;
            o.x = relu(fmaxf(fmaxf(a0[0], a0[1]), fmaxf(a1[0], a1[1])));
            o.y = relu(fmaxf(fmaxf(a0[2], a0[3]), fmaxf(a1[2], a1[3])));
            o.z = relu(fmaxf(fmaxf(a0[4], a0[5]), fmaxf(a1[4], a1[5])));
            o.w = relu(fmaxf(fmaxf(a0[6], a0[7]), fmaxf(a1[6], a1[7])));
            *reinterpret_cast<float4*>(
                &g_feat[b*FEAT_DIM + ((l*16 + c)*16 + py)*16 + xg*4]) = o;
        }
        __syncthreads();
    }
}

// ---- h = relu(feat @ lin_w + lin_b) : 1024x12288 @ 12288x512 ----
__global__ __launch_bounds__(256)
void lin_kernel(const float* __restrict__ Wl, const float* __restrict__ bl)
{
    __shared__ float As[64][33];
    __shared__ float Bs[32][64];
    const int bn = blockIdx.x & 7;
    const int bm = blockIdx.x >> 3;
    const int t  = threadIdx.x;
    const int txg = t & 15, tyg = t >> 4;
    const int j0 = txg * 4, i0 = tyg * 4;
    const int rowBase = bm * 64, colBase = bn * 64;
    float acc[4][4] = {};
    for (int kt = 0; kt < FEAT_DIM; kt += 32) {
        #pragma unroll
        for (int r = 0; r < 8; r++) {
            int idx = t + r*256;
            int row = idx >> 5, kk = idx & 31;
            As[row][kk] = g_feat[(rowBase + row)*FEAT_DIM + kt + kk];
        }
        #pragma unroll
        for (int r = 0; r < 8; r++) {
            int idx = t + r*256;
            int row = idx >> 6, col = idx & 63;
            Bs[row][col] = Wl[(kt + row)*512 + colBase + col];
        }
        __syncthreads();
        #pragma unroll
        for (int k = 0; k < 32; k++) {
            float4 bv = *reinterpret_cast<const float4*>(&Bs[k][j0]);
            #pragma unroll
            for (int r = 0; r < 4; r++) {
                float a = As[i0 + r][k];
                acc[r][0] += a*bv.x; acc[r][1] += a*bv.y; acc[r][2] += a*bv.z; acc[r][3] += a*bv.w;
            }
        }
        __syncthreads();
    }
    #pragma unroll
    for (int r = 0; r < 4; r++)
        #pragma unroll
        for (int c = 0; c < 4; c++)
            g_hid[(rowBase + i0 + r)*512 + colBase + j0 + c] =
                fmaxf(acc[r][c] + bl[colBase + j0 + c], 0.f);
}

// ---- out = h @ score_w + score_b : one warp per row ----
__global__ __launch_bounds__(256)
void score_kernel(const float* __restrict__ sw, const float* __restrict__ sb,
                  float* __restrict__ out)
{
    int gw   = (blockIdx.x * blockDim.x + threadIdx.x) >> 5;
    int lane = threadIdx.x & 31;
    if (gw >= NB) return;
    const float* h = g_hid + gw * 512;
    float s = 0.f;
    #pragma unroll
    for (int j = lane; j < 512; j += 32) s += h[j] * sw[j];
    #pragma unroll
    for (int o = 16; o > 0; o >>= 1) s += __shfl_xor_sync(0xFFFFFFFFu, s, o);
    if (lane == 0) out[gw] = s + sb[0];
}

extern "C" void kernel_launch(void* const* d_in, const int* in_sizes, int n_in,
                              void* d_out, int out_size)
{
    const float* x_q  = (const float*)d_in[0];
    const float* x_c  = (const float*)d_in[1];
    const float* w0   = (const float*)d_in[2];
    const float* b0   = (const float*)d_in[3];
    const float* w1   = (const float*)d_in[4];
    const float* b1   = (const float*)d_in[5];
    const float* w2   = (const float*)d_in[6];
    const float* b2   = (const float*)d_in[7];
    const float* c1w  = (const float*)d_in[8];
    const float* c1b  = (const float*)d_in[9];
    const float* c2w  = (const float*)d_in[10];
    const float* c2b  = (const float*)d_in[11];
    const float* linw = (const float*)d_in[12];
    const float* linb = (const float*)d_in[13];
    const float* scw  = (const float*)d_in[14];
    const float* scb  = (const float*)d_in[15];
    const int*   eiq  = (const int*)d_in[16];
    const int*   eic  = (const int*)d_in[17];

    cudaFuncSetAttribute(fused_kernel, cudaFuncAttributeMaxDynamicSharedMemorySize, SMEM_BYTES);

    fused_kernel<<<NB, 512, SMEM_BYTES>>>(x_q, x_c, w0, b0, w1, b1, w2, b2,
                                          c1w, c1b, c2w, c2b, eiq, eic);
    lin_kernel<<<128, 256>>>(linw, linb);
    score_kernel<<<128, 256>>>(scw, scb, (float*)d_out);
}

// round 4
// speedup vs baseline: 2.0144x; 1.1001x over previous
#include <cuda_runtime.h>

#define NB 1024
#define NN 64
#define DD 128
#define NE 512
#define BE (NB*NE)
#define HS 132                 // padded smem row stride (float4-aligned)
#define HSZ (NN*HS)            // 8448 floats
#define SIMS_S 72              // 4 pad | 64 data | 4 pad
#define P1S 40                 // 4 pad | 32 data | 4 pad
#define FEAT_DIM 12288

// static device scratch (allocation-free rule)
__device__ float g_feat[NB*FEAT_DIM];
__device__ float g_hid[NB*512];

// smem: Hq[HSZ] Hc[HSZ] Mq[HSZ] Mc[HSZ] tail
#define TAIL_WORDS 5962
#define SMEM_WORDS (4*HSZ + TAIL_WORDS)
#define SMEM_BYTES (SMEM_WORDS*4)

__device__ __forceinline__ float relu(float v) { return fmaxf(v, 0.f); }

__global__ __launch_bounds__(512, 1)
void fused_kernel(const float* __restrict__ x_q, const float* __restrict__ x_c,
                  const float* __restrict__ w0, const float* __restrict__ b0,
                  const float* __restrict__ w1, const float* __restrict__ b1,
                  const float* __restrict__ w2, const float* __restrict__ b2,
                  const float* __restrict__ c1w, const float* __restrict__ c1b,
                  const float* __restrict__ c2w, const float* __restrict__ c2b,
                  const int* __restrict__ eiq, const int* __restrict__ eic)
{
    extern __shared__ float sm[];
    float* Hq = sm;
    float* Hc = Hq + HSZ;
    float* Mq = Hc + HSZ;
    float* Mc = Mq + HSZ;
    // conv-phase aliases of the M region (GEMM outputs dead by then)
    float* sims = Mq;                 // 64*72 = 4608
    float* p1   = Mq + 4608;          // 8*32*40 = 10240
    float* tail = sm + 4*HSZ;
    int*   off_q = (int*)tail;        // 65
    int*   off_c = off_q + 65;        // 65
    int*   cntq  = off_c + 65;        // 64
    int*   cntc  = cntq + 64;         // 64
    int*   curq  = cntc + 64;         // 64
    int*   curc  = curq + 64;         // 64
    int*   csq   = curc + 64;         // 512
    int*   csc   = csq + 512;         // 512
    float* cnq   = (float*)(csc + 512); // 512
    float* cnc   = cnq + 512;         // 512
    float* disq  = cnc + 512;         // 64
    float* disc  = disq + 64;         // 64
    float* w1t   = disc + 64;         // 200  : [(dy*5+dx)*8 + c]
    float* w2t   = w1t + 200;         // 3200 : [((ci*5+dy)*5+dx)*16 + c]

    const int b    = blockIdx.x;
    const int t    = threadIdx.x;
    const int base = b * NN;

    // ---- load node features (both graphs), vectorized ----
    for (int idx = t; idx < NN*DD/4; idx += 512) {
        int i = idx >> 5, k4 = (idx & 31) * 4;
        *reinterpret_cast<float4*>(&Hq[i*HS + k4]) =
            *reinterpret_cast<const float4*>(&x_q[(base + i)*DD + k4]);
        *reinterpret_cast<float4*>(&Hc[i*HS + k4]) =
            *reinterpret_cast<const float4*>(&x_c[(base + i)*DD + k4]);
    }
    if (t < 64) { cntq[t] = 0; cntc[t] = 0; }
    __syncthreads();

    // ---- edges: degree count; stage packed (s,d) in (dead) M region ----
    int* tq = (int*)Mq;
    int* tc = (int*)Mc;
    if (t < NE) {
        int e = b*NE + t;
        int s = eiq[e] - base, d = eiq[BE + e] - base;
        tq[t] = (s << 8) | d;
        atomicAdd(&cntq[d], 1);
        s = eic[e] - base; d = eic[BE + e] - base;
        tc[t] = (s << 8) | d;
        atomicAdd(&cntc[d], 1);
    }
    __syncthreads();
    if (t < 64)        disq[t]      = rsqrtf((float)cntq[t] + 1.0f);
    else if (t < 128)  disc[t - 64] = rsqrtf((float)cntc[t - 64] + 1.0f);
    if (t == 0)  { int a = 0; for (int i = 0; i < 64; i++){ off_q[i] = a; a += cntq[i]; } off_q[64] = a; }
    if (t == 32) { int a = 0; for (int i = 0; i < 64; i++){ off_c[i] = a; a += cntc[i]; } off_c[64] = a; }
    __syncthreads();
    if (t < 64) { curq[t] = off_q[t]; curc[t] = off_c[t]; }
    __syncthreads();
    if (t < NE) {
        int sd = tq[t]; int s = sd >> 8, d = sd & 255;
        int p = atomicAdd(&curq[d], 1);
        csq[p] = s; cnq[p] = disq[s] * disq[d];
        sd = tc[t]; s = sd >> 8; d = sd & 255;
        p = atomicAdd(&curc[d], 1);
        csc[p] = s; cnc[p] = disc[s] * disc[d];
    }
    __syncthreads();

    for (int l = 0; l < 3; l++) {
        const float* W  = (l == 0) ? w0 : (l == 1) ? w1 : w2;
        const float* bb = (l == 0) ? b0 : (l == 1) ? b1 : b2;

        // ---- GEMM: M = (relu?)(H) @ W, both graphs, 4x4 micro-tiles, float4 k ----
        {
            const int j0 = (t & 31) * 4, i0 = (t >> 5) * 4;
            float4 aq[4], ac[4];
            #pragma unroll
            for (int r = 0; r < 4; r++) { aq[r] = make_float4(0,0,0,0); ac[r] = make_float4(0,0,0,0); }
            for (int k = 0; k < DD; k += 4) {
                float4 hq[4], hc[4];
                #pragma unroll
                for (int r = 0; r < 4; r++) {
                    hq[r] = *reinterpret_cast<const float4*>(&Hq[(i0 + r)*HS + k]);
                    hc[r] = *reinterpret_cast<const float4*>(&Hc[(i0 + r)*HS + k]);
                    if (l) {
                        hq[r].x = relu(hq[r].x); hq[r].y = relu(hq[r].y);
                        hq[r].z = relu(hq[r].z); hq[r].w = relu(hq[r].w);
                        hc[r].x = relu(hc[r].x); hc[r].y = relu(hc[r].y);
                        hc[r].z = relu(hc[r].z); hc[r].w = relu(hc[r].w);
                    }
                }
                #pragma unroll
                for (int kk = 0; kk < 4; kk++) {
                    float4 wv = *reinterpret_cast<const float4*>(W + (k + kk)*DD + j0);
                    #pragma unroll
                    for (int r = 0; r < 4; r++) {
                        float a = kk == 0 ? hq[r].x : kk == 1 ? hq[r].y : kk == 2 ? hq[r].z : hq[r].w;
                        aq[r].x += a*wv.x; aq[r].y += a*wv.y; aq[r].z += a*wv.z; aq[r].w += a*wv.w;
                        float c = kk == 0 ? hc[r].x : kk == 1 ? hc[r].y : kk == 2 ? hc[r].z : hc[r].w;
                        ac[r].x += c*wv.x; ac[r].y += c*wv.y; ac[r].z += c*wv.z; ac[r].w += c*wv.w;
                    }
                }
            }
            #pragma unroll
            for (int r = 0; r < 4; r++) {
                *reinterpret_cast<float4*>(&Mq[(i0 + r)*HS + j0]) = aq[r];
                *reinterpret_cast<float4*>(&Mc[(i0 + r)*HS + j0]) = ac[r];
            }
        }
        __syncthreads();

        // ---- aggregate via CSR: out = b + dis^2*M[i] + sum M[src]*norm ; into H ----
        {
            const int f = t & 127, g = t >> 7;   // g in 0..3
            float bf = bb[f];
            #pragma unroll 1
            for (int r = 0; r < 16; r++) {
                int i = g + (r << 2);
                float acc = bf + disq[i]*disq[i]*Mq[i*HS + f];
                int e0 = off_q[i], e1 = off_q[i + 1];
                for (int p = e0; p < e1; p++) acc += Mq[csq[p]*HS + f] * cnq[p];
                Hq[i*HS + f] = acc;
                acc = bf + disc[i]*disc[i]*Mc[i*HS + f];
                e0 = off_c[i]; e1 = off_c[i + 1];
                for (int p = e0; p < e1; p++) acc += Mc[csc[p]*HS + f] * cnc[p];
                Hc[i*HS + f] = acc;
            }
        }
        __syncthreads();

        // ---- sims = out_q @ out_c^T (pre-relu), 4i x {j, j+32}, float4 k ----
        {
            const int j = t & 31, ig = t >> 5;   // i0 = ig*4
            float acc[4][2] = {};
            for (int k = 0; k < DD; k += 4) {
                float4 ca = *reinterpret_cast<const float4*>(&Hc[j*HS + k]);
                float4 cb = *reinterpret_cast<const float4*>(&Hc[(j + 32)*HS + k]);
                #pragma unroll
                for (int r = 0; r < 4; r++) {
                    float4 qv = *reinterpret_cast<const float4*>(&Hq[(ig*4 + r)*HS + k]);
                    acc[r][0] += qv.x*ca.x; acc[r][0] += qv.y*ca.y;
                    acc[r][0] += qv.z*ca.z; acc[r][0] += qv.w*ca.w;
                    acc[r][1] += qv.x*cb.x; acc[r][1] += qv.y*cb.y;
                    acc[r][1] += qv.z*cb.z; acc[r][1] += qv.w*cb.w;
                }
            }
            #pragma unroll
            for (int r = 0; r < 4; r++) {
                sims[(ig*4 + r)*SIMS_S + 4 + j]      = acc[r][0];
                sims[(ig*4 + r)*SIMS_S + 4 + j + 32] = acc[r][1];
            }
        }
        // zero the column pads of sims (64 rows x 8) and p1 (256 rows x 8)
        for (int idx = t; idx < 2560; idx += 512) {
            if (idx < 512) {
                int row = idx >> 3, pc = idx & 7;
                sims[row*SIMS_S + (pc < 4 ? pc : pc + 64)] = 0.f;
            } else {
                int k2 = idx - 512;
                int row = k2 >> 3, pc = k2 & 7;
                p1[row*P1S + (pc < 4 ? pc : pc + 32)] = 0.f;
            }
        }
        // stage conv weights, channel-transposed for float2 broadcast reads
        for (int idx = t; idx < 200; idx += 512) {
            int c = idx & 7, rest = idx >> 3;                    // rest = dy*5+dx
            w1t[idx] = c1w[l*200 + c*25 + rest];
        }
        for (int idx = t; idx < 3200; idx += 512) {
            int c = idx & 15, rest = idx >> 4;                   // rest = (ci*5+dy)*5+dx
            int dxx = rest % 5, r2 = rest / 5;
            int dyy = r2 % 5, ci = r2 / 5;
            w2t[idx] = c2w[l*3200 + (c*8 + ci)*25 + dyy*5 + dxx];
        }
        __syncthreads();

        // ---- conv1 (1->8,5x5,pad2)+relu+pool2 -> p1 ; 2 channels/thread ----
        #pragma unroll 1
        for (int it = 0; it < 2; it++) {
            int item = it*512 + t;                 // 1024 items
            int xg = item & 7, py = (item >> 3) & 31, cp = item >> 8;  // cp 0..3
            int Xc = xg * 8, Y = py * 2;
            int c0 = cp * 2;
            float bias0 = c1b[l*8 + c0], bias1 = c1b[l*8 + c0 + 1];
            float a00[8], a01[8], a10[8], a11[8];  // a<ch><convrow>
            #pragma unroll
            for (int j = 0; j < 8; j++) { a00[j]=bias0; a01[j]=bias0; a10[j]=bias1; a11[j]=bias1; }
            float2 prev[5];
            #pragma unroll
            for (int d = 0; d < 5; d++) prev[d] = make_float2(0.f, 0.f);
            #pragma unroll
            for (int iy6 = 0; iy6 < 6; iy6++) {
                int iy = Y - 2 + iy6;
                float in[16];
                if ((unsigned)iy < 64u) {
                    const float* rp = &sims[iy*SIMS_S + Xc];
                    float4 v0 = *reinterpret_cast<const float4*>(rp);
                    float4 v1 = *reinterpret_cast<const float4*>(rp + 4);
                    float4 v2 = *reinterpret_cast<const float4*>(rp + 8);
                    float4 v3 = *reinterpret_cast<const float4*>(rp + 12);
                    in[0]=v0.x; in[1]=v0.y; in[2]=v0.z; in[3]=v0.w;
                    in[4]=v1.x; in[5]=v1.y; in[6]=v1.z; in[7]=v1.w;
                    in[8]=v2.x; in[9]=v2.y; in[10]=v2.z; in[11]=v2.w;
                    in[12]=v3.x; in[13]=v3.y; in[14]=v3.z; in[15]=v3.w;
                } else {
                    #pragma unroll
                    for (int i = 0; i < 16; i++) in[i] = 0.f;
                }
                float2 cur[5];
                #pragma unroll
                for (int d = 0; d < 5; d++)
                    cur[d] = (iy6 < 5)
                        ? *reinterpret_cast<const float2*>(&w1t[(iy6*5 + d)*8 + c0])
                        : make_float2(0.f, 0.f);
                #pragma unroll
                for (int d = 0; d < 5; d++) {
                    #pragma unroll
                    for (int j = 0; j < 8; j++) {
                        float x = in[j + d + 2];
                        a00[j] += x * cur[d].x;
                        a10[j] += x * cur[d].y;
                        a01[j] += x * prev[d].x;
                        a11[j] += x * prev[d].y;
                    }
                }
                #pragma unroll
                for (int d = 0; d < 5; d++) prev[d] = cur[d];
            }
            float4 o0, o1;
            o0.x = relu(fmaxf(fmaxf(a00[0],a00[1]), fmaxf(a01[0],a01[1])));
            o0.y = relu(fmaxf(fmaxf(a00[2],a00[3]), fmaxf(a01[2],a01[3])));
            o0.z = relu(fmaxf(fmaxf(a00[4],a00[5]), fmaxf(a01[4],a01[5])));
            o0.w = relu(fmaxf(fmaxf(a00[6],a00[7]), fmaxf(a01[6],a01[7])));
            o1.x = relu(fmaxf(fmaxf(a10[0],a10[1]), fmaxf(a11[0],a11[1])));
            o1.y = relu(fmaxf(fmaxf(a10[2],a10[3]), fmaxf(a11[2],a11[3])));
            o1.z = relu(fmaxf(fmaxf(a10[4],a10[5]), fmaxf(a11[4],a11[5])));
            o1.w = relu(fmaxf(fmaxf(a10[6],a10[7]), fmaxf(a11[6],a11[7])));
            *reinterpret_cast<float4*>(&p1[(c0*32 + py)*P1S + 4 + xg*4])       = o0;
            *reinterpret_cast<float4*>(&p1[((c0+1)*32 + py)*P1S + 4 + xg*4])   = o1;
        }
        __syncthreads();

        // ---- conv2 (8->16,5x5,pad2)+relu+pool2 -> g_feat ; 2 channels/thread ----
        {
            int xg = t & 3, py = (t >> 2) & 15, cp = t >> 6;   // cp 0..7, warp-uniform
            int Xc = xg * 8, Y = py * 2;
            int c0 = cp * 2;
            float bias0 = c2b[l*16 + c0], bias1 = c2b[l*16 + c0 + 1];
            float a00[8], a01[8], a10[8], a11[8];
            #pragma unroll
            for (int j = 0; j < 8; j++) { a00[j]=bias0; a01[j]=bias0; a10[j]=bias1; a11[j]=bias1; }
            #pragma unroll 1
            for (int ci = 0; ci < 8; ci++) {
                const float* pch = p1 + ci*32*P1S;
                const float* wch = w2t + ci*25*16;
                float2 prev[5];
                #pragma unroll
                for (int d = 0; d < 5; d++) prev[d] = make_float2(0.f, 0.f);
                #pragma unroll
                for (int iy6 = 0; iy6 < 6; iy6++) {
                    int iy = Y - 2 + iy6;
                    float in[16];
                    if ((unsigned)iy < 32u) {
                        const float* rp = pch + iy*P1S + Xc;
                        float4 v0 = *reinterpret_cast<const float4*>(rp);
                        float4 v1 = *reinterpret_cast<const float4*>(rp + 4);
                        float4 v2 = *reinterpret_cast<const float4*>(rp + 8);
                        float4 v3 = *reinterpret_cast<const float4*>(rp + 12);
                        in[0]=v0.x; in[1]=v0.y; in[2]=v0.z; in[3]=v0.w;
                        in[4]=v1.x; in[5]=v1.y; in[6]=v1.z; in[7]=v1.w;
                        in[8]=v2.x; in[9]=v2.y; in[10]=v2.z; in[11]=v2.w;
                        in[12]=v3.x; in[13]=v3.y; in[14]=v3.z; in[15]=v3.w;
                    } else {
                        #pragma unroll
                        for (int i = 0; i < 16; i++) in[i] = 0.f;
                    }
                    float2 cur[5];
                    #pragma unroll
                    for (int d = 0; d < 5; d++)
                        cur[d] = (iy6 < 5)
                            ? *reinterpret_cast<const float2*>(&wch[(iy6*5 + d)*16 + c0])
                            : make_float2(0.f, 0.f);
                    #pragma unroll
                    for (int d = 0; d < 5; d++) {
                        #pragma unroll
                        for (int j = 0; j < 8; j++) {
                            float x = in[j + d + 2];
                            a00[j] += x * cur[d].x;
                            a10[j] += x * cur[d].y;
                            a01[j] += x * prev[d].x;
                            a11[j] += x * prev[d].y;
                        }
                    }
                    #pragma unroll
                    for (int d = 0; d < 5; d++) prev[d] = cur[d];
                }
            }
            float4 o0, o1;
            o0.x = relu(fmaxf(fmaxf(a00[0],a00[1]), fmaxf(a01[0],a01[1])));
            o0.y = relu(fmaxf(fmaxf(a00[2],a00[3]), fmaxf(a01[2],a01[3])));
            o0.z = relu(fmaxf(fmaxf(a00[4],a00[5]), fmaxf(a01[4],a01[5])));
            o0.w = relu(fmaxf(fmaxf(a00[6],a00[7]), fmaxf(a01[6],a01[7])));
            o1.x = relu(fmaxf(fmaxf(a10[0],a10[1]), fmaxf(a11[0],a11[1])));
            o1.y = relu(fmaxf(fmaxf(a10[2],a10[3]), fmaxf(a11[2],a11[3])));
            o1.z = relu(fmaxf(fmaxf(a10[4],a10[5]), fmaxf(a11[4],a11[5])));
            o1.w = relu(fmaxf(fmaxf(a10[6],a10[7]), fmaxf(a11[6],a11[7])));
            *reinterpret_cast<float4*>(
                &g_feat[b*FEAT_DIM + ((l*16 + c0)*16 + py)*16 + xg*4])     = o0;
            *reinterpret_cast<float4*>(
                &g_feat[b*FEAT_DIM + ((l*16 + c0 + 1)*16 + py)*16 + xg*4]) = o1;
        }
        __syncthreads();
    }
}

// ---- h = relu(feat @ lin_w + lin_b) : 1024x12288 @ 12288x512 ----
__global__ __launch_bounds__(256)
void lin_kernel(const float* __restrict__ Wl, const float* __restrict__ bl)
{
    __shared__ float As[64][33];
    __shared__ float Bs[32][68];           // stride 68: odd 16B units -> conflict-free
    const int bn = blockIdx.x & 7;
    const int bm = blockIdx.x >> 3;
    const int t  = threadIdx.x;
    const int txg = t & 15, tyg = t >> 4;
    const int j0 = txg * 4, i0 = tyg * 4;
    const int rowBase = bm * 64, colBase = bn * 64;
    float acc[4][4] = {};
    for (int kt = 0; kt < FEAT_DIM; kt += 32) {
        #pragma unroll
        for (int r = 0; r < 8; r++) {
            int idx = t + r*256;
            int row = idx >> 5, kk = idx & 31;
            As[row][kk] = g_feat[(rowBase + row)*FEAT_DIM + kt + kk];
        }
        #pragma unroll
        for (int r = 0; r < 8; r++) {
            int idx = t + r*256;
            int row = idx >> 6, col = idx & 63;
            Bs[row][col] = Wl[(kt + row)*512 + colBase + col];
        }
        __syncthreads();
        #pragma unroll
        for (int k = 0; k < 32; k++) {
            float4 bv = *reinterpret_cast<const float4*>(&Bs[k][j0]);
            #pragma unroll
            for (int r = 0; r < 4; r++) {
                float a = As[i0 + r][k];
                acc[r][0] += a*bv.x; acc[r][1] += a*bv.y; acc[r][2] += a*bv.z; acc[r][3] += a*bv.w;
            }
        }
        __syncthreads();
    }
    #pragma unroll
    for (int r = 0; r < 4; r++)
        #pragma unroll
        for (int c = 0; c < 4; c++)
            g_hid[(rowBase + i0 + r)*512 + colBase + j0 + c] =
                fmaxf(acc[r][c] + bl[colBase + j0 + c], 0.f);
}

// ---- out = h @ score_w + score_b : one warp per row ----
__global__ __launch_bounds__(256)
void score_kernel(const float* __restrict__ sw, const float* __restrict__ sb,
                  float* __restrict__ out)
{
    int gw   = (blockIdx.x * blockDim.x + threadIdx.x) >> 5;
    int lane = threadIdx.x & 31;
    if (gw >= NB) return;
    const float* h = g_hid + gw * 512;
    float s = 0.f;
    #pragma unroll
    for (int j = lane; j < 512; j += 32) s += h[j] * sw[j];
    #pragma unroll
    for (int o = 16; o > 0; o >>= 1) s += __shfl_xor_sync(0xFFFFFFFFu, s, o);
    if (lane == 0) out[gw] = s + sb[0];
}

extern "C" void kernel_launch(void* const* d_in, const int* in_sizes, int n_in,
                              void* d_out, int out_size)
{
    const float* x_q  = (const float*)d_in[0];
    const float* x_c  = (const float*)d_in[1];
    const float* w0   = (const float*)d_in[2];
    const float* b0   = (const float*)d_in[3];
    const float* w1   = (const float*)d_in[4];
    const float* b1   = (const float*)d_in[5];
    const float* w2   = (const float*)d_in[6];
    const float* b2   = (const float*)d_in[7];
    const float* c1w  = (const float*)d_in[8];
    const float* c1b  = (const float*)d_in[9];
    const float* c2w  = (const float*)d_in[10];
    const float* c2b  = (const float*)d_in[11];
    const float* linw = (const float*)d_in[12];
    const float* linb = (const float*)d_in[13];
    const float* scw  = (const float*)d_in[14];
    const float* scb  = (const float*)d_in[15];
    const int*   eiq  = (const int*)d_in[16];
    const int*   eic  = (const int*)d_in[17];

    cudaFuncSetAttribute(fused_kernel, cudaFuncAttributeMaxDynamicSharedMemorySize, SMEM_BYTES);

    fused_kernel<<<NB, 512, SMEM_BYTES>>>(x_q, x_c, w0, b0, w1, b1, w2, b2,
                                          c1w, c1b, c2w, c2b, eiq, eic);
    lin_kernel<<<128, 256>>>(linw, linb);
    score_kernel<<<128, 256>>>(scw, scb, (float*)d_out);
}

// round 5
// speedup vs baseline: 2.2756x; 1.1296x over previous
#include <cuda_runtime.h>

#define NB 1024
#define NN 64
#define DD 128
#define NE 512
#define BE (NB*NE)
#define HS 132                 // padded smem row stride (float4-aligned)
#define HSZ (NN*HS)            // 8448 floats
#define SIMS_S 72              // 4 pad | 64 data | 4 pad
#define P1S 40                 // 4 pad | 32 data | 4 pad
#define FEAT_DIM 12288

typedef unsigned long long u64;

__device__ float g_feat[NB*FEAT_DIM];
__device__ float g_hid[NB*512];

#define TAIL_WORDS 5962
#define SMEM_WORDS (4*HSZ + TAIL_WORDS)
#define SMEM_BYTES (SMEM_WORDS*4)

__device__ __forceinline__ float relu(float v) { return fmaxf(v, 0.f); }

__device__ __forceinline__ u64 dup2(float v) {
    u64 r; asm("mov.b64 %0, {%1, %1};" : "=l"(r) : "f"(v)); return r;
}
__device__ __forceinline__ u64 pk2(float x, float y) {
    u64 r; asm("mov.b64 %0, {%1, %2};" : "=l"(r) : "f"(x), "f"(y)); return r;
}
__device__ __forceinline__ float2 upk(u64 v) {
    float2 r; asm("mov.b64 {%0, %1}, %2;" : "=f"(r.x), "=f"(r.y) : "l"(v)); return r;
}
__device__ __forceinline__ void fma2(u64 &d, u64 a, u64 b) {
    asm("fma.rn.f32x2 %0, %1, %2, %0;" : "+l"(d) : "l"(a), "l"(b));
}

__global__ __launch_bounds__(512, 1)
void fused_kernel(const float* __restrict__ x_q, const float* __restrict__ x_c,
                  const float* __restrict__ w0, const float* __restrict__ b0,
                  const float* __restrict__ w1, const float* __restrict__ b1,
                  const float* __restrict__ w2, const float* __restrict__ b2,
                  const float* __restrict__ c1w, const float* __restrict__ c1b,
                  const float* __restrict__ c2w, const float* __restrict__ c2b,
                  const int* __restrict__ eiq, const int* __restrict__ eic)
{
    extern __shared__ __align__(16) float sm[];
    float* Hq = sm;
    float* Hc = Hq + HSZ;
    float* Mq = Hc + HSZ;
    float* Mc = Mq + HSZ;
    float* sims = Mq;                 // 64*72 = 4608
    float* p1   = Mq + 4608;          // 8*32*40 = 10240
    float* tail = sm + 4*HSZ;
    int*   off_q = (int*)tail;        // 65
    int*   off_c = off_q + 65;        // 65
    int*   cntq  = off_c + 65;        // 64
    int*   cntc  = cntq + 64;         // 64
    int*   curq  = cntc + 64;         // 64
    int*   curc  = curq + 64;         // 64
    int*   csq   = curc + 64;         // 512
    int*   csc   = csq + 512;         // 512
    float* cnq   = (float*)(csc + 512); // 512
    float* cnc   = cnq + 512;         // 512
    float* disq  = cnc + 512;         // 64
    float* disc  = disq + 64;         // 64
    float* w1t   = disc + 64;         // 200  : [(dy*5+dx)*8 + c]   (offset even -> 8B ok)
    float* w2t   = w1t + 200;         // 3200 : [((ci*5+dy)*5+dx)*16 + c]

    const int b    = blockIdx.x;
    const int t    = threadIdx.x;
    const int base = b * NN;

    // ---- load node features, vectorized ----
    for (int idx = t; idx < NN*DD/4; idx += 512) {
        int i = idx >> 5, k4 = (idx & 31) * 4;
        *reinterpret_cast<float4*>(&Hq[i*HS + k4]) =
            *reinterpret_cast<const float4*>(&x_q[(base + i)*DD + k4]);
        *reinterpret_cast<float4*>(&Hc[i*HS + k4]) =
            *reinterpret_cast<const float4*>(&x_c[(base + i)*DD + k4]);
    }
    if (t < 64) { cntq[t] = 0; cntc[t] = 0; }
    __syncthreads();

    // ---- edges: degree count; stage packed (s,d) in dead M region ----
    int* tq = (int*)Mq;
    int* tc = (int*)Mc;
    if (t < NE) {
        int e = b*NE + t;
        int s = eiq[e] - base, d = eiq[BE + e] - base;
        tq[t] = (s << 8) | d;
        atomicAdd(&cntq[d], 1);
        s = eic[e] - base; d = eic[BE + e] - base;
        tc[t] = (s << 8) | d;
        atomicAdd(&cntc[d], 1);
    }
    __syncthreads();
    if (t < 64)        disq[t]      = rsqrtf((float)cntq[t] + 1.0f);
    else if (t < 128)  disc[t - 64] = rsqrtf((float)cntc[t - 64] + 1.0f);
    if (t == 0)  { int a = 0; for (int i = 0; i < 64; i++){ off_q[i] = a; a += cntq[i]; } off_q[64] = a; }
    if (t == 32) { int a = 0; for (int i = 0; i < 64; i++){ off_c[i] = a; a += cntc[i]; } off_c[64] = a; }
    __syncthreads();
    if (t < 64) { curq[t] = off_q[t]; curc[t] = off_c[t]; }
    __syncthreads();
    if (t < NE) {
        int sd = tq[t]; int s = sd >> 8, d = sd & 255;
        int p = atomicAdd(&curq[d], 1);
        csq[p] = s; cnq[p] = disq[s] * disq[d];
        sd = tc[t]; s = sd >> 8; d = sd & 255;
        p = atomicAdd(&curc[d], 1);
        csc[p] = s; cnc[p] = disc[s] * disc[d];
    }
    __syncthreads();

    for (int l = 0; l < 3; l++) {
        const float* W  = (l == 0) ? w0 : (l == 1) ? w1 : w2;
        const float* bb = (l == 0) ? b0 : (l == 1) ? b1 : b2;

        // ---- GEMM: M = (relu?)(H) @ W, f32x2 j-packed ----
        {
            const int j0 = (t & 31) * 4, i0 = (t >> 5) * 4;
            u64 aq2[4][2] = {}, ac2[4][2] = {};
            for (int k = 0; k < DD; k += 4) {
                float4 hq[4], hc[4];
                #pragma unroll
                for (int r = 0; r < 4; r++) {
                    hq[r] = *reinterpret_cast<const float4*>(&Hq[(i0 + r)*HS + k]);
                    hc[r] = *reinterpret_cast<const float4*>(&Hc[(i0 + r)*HS + k]);
                    if (l) {
                        hq[r].x = relu(hq[r].x); hq[r].y = relu(hq[r].y);
                        hq[r].z = relu(hq[r].z); hq[r].w = relu(hq[r].w);
                        hc[r].x = relu(hc[r].x); hc[r].y = relu(hc[r].y);
                        hc[r].z = relu(hc[r].z); hc[r].w = relu(hc[r].w);
                    }
                }
                #pragma unroll
                for (int kk = 0; kk < 4; kk++) {
                    ulonglong2 wv = *reinterpret_cast<const ulonglong2*>(W + (k + kk)*DD + j0);
                    #pragma unroll
                    for (int r = 0; r < 4; r++) {
                        float aqv = kk == 0 ? hq[r].x : kk == 1 ? hq[r].y : kk == 2 ? hq[r].z : hq[r].w;
                        u64 ad = dup2(aqv);
                        fma2(aq2[r][0], ad, wv.x);
                        fma2(aq2[r][1], ad, wv.y);
                        float acv = kk == 0 ? hc[r].x : kk == 1 ? hc[r].y : kk == 2 ? hc[r].z : hc[r].w;
                        u64 cd = dup2(acv);
                        fma2(ac2[r][0], cd, wv.x);
                        fma2(ac2[r][1], cd, wv.y);
                    }
                }
            }
            #pragma unroll
            for (int r = 0; r < 4; r++) {
                ulonglong2 sq; sq.x = aq2[r][0]; sq.y = aq2[r][1];
                ulonglong2 sc; sc.x = ac2[r][0]; sc.y = ac2[r][1];
                *reinterpret_cast<ulonglong2*>(&Mq[(i0 + r)*HS + j0]) = sq;
                *reinterpret_cast<ulonglong2*>(&Mc[(i0 + r)*HS + j0]) = sc;
            }
        }
        __syncthreads();

        // ---- aggregate via CSR, feature pairs (u64) ----
        {
            const int f2 = (t & 63) * 2, g = t >> 6;   // g in 0..7
            u64 bf2 = *reinterpret_cast<const u64*>(&bb[f2]);
            #pragma unroll 1
            for (int r = 0; r < 8; r++) {
                int i = g + (r << 3);
                u64 acc = bf2;
                fma2(acc, dup2(disq[i]*disq[i]), *reinterpret_cast<const u64*>(&Mq[i*HS + f2]));
                int e0 = off_q[i], e1 = off_q[i + 1];
                for (int p = e0; p < e1; p++)
                    fma2(acc, dup2(cnq[p]), *reinterpret_cast<const u64*>(&Mq[csq[p]*HS + f2]));
                *reinterpret_cast<u64*>(&Hq[i*HS + f2]) = acc;
                acc = bf2;
                fma2(acc, dup2(disc[i]*disc[i]), *reinterpret_cast<const u64*>(&Mc[i*HS + f2]));
                e0 = off_c[i]; e1 = off_c[i + 1];
                for (int p = e0; p < e1; p++)
                    fma2(acc, dup2(cnc[p]), *reinterpret_cast<const u64*>(&Mc[csc[p]*HS + f2]));
                *reinterpret_cast<u64*>(&Hc[i*HS + f2]) = acc;
            }
        }
        __syncthreads();

        // ---- sims = out_q @ out_c^T, f32x2 k-packed (zero-cost pairs) ----
        {
            const int j = t & 31, ig = t >> 5;
            u64 a2[4][2] = {};
            for (int k = 0; k < DD; k += 4) {
                ulonglong2 ca = *reinterpret_cast<const ulonglong2*>(&Hc[j*HS + k]);
                ulonglong2 cb = *reinterpret_cast<const ulonglong2*>(&Hc[(j + 32)*HS + k]);
                #pragma unroll
                for (int r = 0; r < 4; r++) {
                    ulonglong2 qv = *reinterpret_cast<const ulonglong2*>(&Hq[(ig*4 + r)*HS + k]);
                    fma2(a2[r][0], qv.x, ca.x);
                    fma2(a2[r][0], qv.y, ca.y);
                    fma2(a2[r][1], qv.x, cb.x);
                    fma2(a2[r][1], qv.y, cb.y);
                }
            }
            #pragma unroll
            for (int r = 0; r < 4; r++) {
                float2 s0 = upk(a2[r][0]);
                float2 s1 = upk(a2[r][1]);
                sims[(ig*4 + r)*SIMS_S + 4 + j]      = s0.x + s0.y;
                sims[(ig*4 + r)*SIMS_S + 4 + j + 32] = s1.x + s1.y;
            }
        }
        // zero the column pads of sims and p1
        for (int idx = t; idx < 2560; idx += 512) {
            if (idx < 512) {
                int row = idx >> 3, pc = idx & 7;
                sims[row*SIMS_S + (pc < 4 ? pc : pc + 64)] = 0.f;
            } else {
                int k2 = idx - 512;
                int row = k2 >> 3, pc = k2 & 7;
                p1[row*P1S + (pc < 4 ? pc : pc + 32)] = 0.f;
            }
        }
        // stage conv weights, channel-transposed (pairs are u64-loadable)
        for (int idx = t; idx < 200; idx += 512) {
            int c = idx & 7, rest = idx >> 3;
            w1t[idx] = c1w[l*200 + c*25 + rest];
        }
        for (int idx = t; idx < 3200; idx += 512) {
            int c = idx & 15, rest = idx >> 4;
            int dxx = rest % 5, r2 = rest / 5;
            int dyy = r2 % 5, ci = r2 / 5;
            w2t[idx] = c2w[l*3200 + (c*8 + ci)*25 + dyy*5 + dxx];
        }
        __syncthreads();

        // ---- conv1 (1->8,5x5,pad2)+relu+pool2, channel-pair f32x2 ----
        #pragma unroll 1
        for (int it = 0; it < 2; it++) {
            int item = it*512 + t;
            int xg = item & 7, py = (item >> 3) & 31, cp = item >> 8;
            int Xc = xg * 8, Y = py * 2;
            int c0 = cp * 2;
            u64 bias2 = *reinterpret_cast<const u64*>(&c1b[l*8 + c0]);
            u64 A0[8], A1[8];                  // {ch0,ch1} accs, conv rows 0/1
            #pragma unroll
            for (int j = 0; j < 8; j++) { A0[j] = bias2; A1[j] = bias2; }
            u64 pw[5];
            #pragma unroll
            for (int d = 0; d < 5; d++) pw[d] = 0;
            #pragma unroll
            for (int iy6 = 0; iy6 < 6; iy6++) {
                int iy = Y - 2 + iy6;
                float in[16];
                if ((unsigned)iy < 64u) {
                    const float* rp = &sims[iy*SIMS_S + Xc];
                    float4 v0 = *reinterpret_cast<const float4*>(rp);
                    float4 v1 = *reinterpret_cast<const float4*>(rp + 4);
                    float4 v2 = *reinterpret_cast<const float4*>(rp + 8);
                    float4 v3 = *reinterpret_cast<const float4*>(rp + 12);
                    in[0]=v0.x; in[1]=v0.y; in[2]=v0.z; in[3]=v0.w;
                    in[4]=v1.x; in[5]=v1.y; in[6]=v1.z; in[7]=v1.w;
                    in[8]=v2.x; in[9]=v2.y; in[10]=v2.z; in[11]=v2.w;
                    in[12]=v3.x; in[13]=v3.y; in[14]=v3.z; in[15]=v3.w;
                } else {
                    #pragma unroll
                    for (int i = 0; i < 16; i++) in[i] = 0.f;
                }
                u64 cw[5];
                #pragma unroll
                for (int d = 0; d < 5; d++)
                    cw[d] = (iy6 < 5)
                        ? *reinterpret_cast<const u64*>(&w1t[(iy6*5 + d)*8 + c0]) : 0ull;
                #pragma unroll
                for (int d = 0; d < 5; d++) {
                    #pragma unroll
                    for (int j = 0; j < 8; j++) {
                        u64 x2 = dup2(in[j + d + 2]);
                        fma2(A0[j], x2, cw[d]);
                        fma2(A1[j], x2, pw[d]);
                    }
                }
                #pragma unroll
                for (int d = 0; d < 5; d++) pw[d] = cw[d];
            }
            float4 o0, o1;
            {
                float2 q0[8], q1[8];
                #pragma unroll
                for (int j = 0; j < 8; j++) { q0[j] = upk(A0[j]); q1[j] = upk(A1[j]); }
                o0.x = relu(fmaxf(fmaxf(q0[0].x,q0[1].x), fmaxf(q1[0].x,q1[1].x)));
                o0.y = relu(fmaxf(fmaxf(q0[2].x,q0[3].x), fmaxf(q1[2].x,q1[3].x)));
                o0.z = relu(fmaxf(fmaxf(q0[4].x,q0[5].x), fmaxf(q1[4].x,q1[5].x)));
                o0.w = relu(fmaxf(fmaxf(q0[6].x,q0[7].x), fmaxf(q1[6].x,q1[7].x)));
                o1.x = relu(fmaxf(fmaxf(q0[0].y,q0[1].y), fmaxf(q1[0].y,q1[1].y)));
                o1.y = relu(fmaxf(fmaxf(q0[2].y,q0[3].y), fmaxf(q1[2].y,q1[3].y)));
                o1.z = relu(fmaxf(fmaxf(q0[4].y,q0[5].y), fmaxf(q1[4].y,q1[5].y)));
                o1.w = relu(fmaxf(fmaxf(q0[6].y,q0[7].y), fmaxf(q1[6].y,q1[7].y)));
            }
            *reinterpret_cast<float4*>(&p1[(c0*32 + py)*P1S + 4 + xg*4])     = o0;
            *reinterpret_cast<float4*>(&p1[((c0+1)*32 + py)*P1S + 4 + xg*4]) = o1;
        }
        __syncthreads();

        // ---- conv2 (8->16,5x5,pad2)+relu+pool2, channel-pair f32x2 ----
        {
            int xg = t & 3, py = (t >> 2) & 15, cp = t >> 6;
            int Xc = xg * 8, Y = py * 2;
            int c0 = cp * 2;
            u64 bias2 = *reinterpret_cast<const u64*>(&c2b[l*16 + c0]);
            u64 A0[8], A1[8];
            #pragma unroll
            for (int j = 0; j < 8; j++) { A0[j] = bias2; A1[j] = bias2; }
            #pragma unroll 1
            for (int ci = 0; ci < 8; ci++) {
                const float* pch = p1 + ci*32*P1S;
                const float* wch = w2t + ci*400;
                u64 pw[5];
                #pragma unroll
                for (int d = 0; d < 5; d++) pw[d] = 0;
                #pragma unroll
                for (int iy6 = 0; iy6 < 6; iy6++) {
                    int iy = Y - 2 + iy6;
                    float in[16];
                    if ((unsigned)iy < 32u) {
                        const float* rp = pch + iy*P1S + Xc;
                        float4 v0 = *reinterpret_cast<const float4*>(rp);
                        float4 v1 = *reinterpret_cast<const float4*>(rp + 4);
                        float4 v2 = *reinterpret_cast<const float4*>(rp + 8);
                        float4 v3 = *reinterpret_cast<const float4*>(rp + 12);
                        in[0]=v0.x; in[1]=v0.y; in[2]=v0.z; in[3]=v0.w;
                        in[4]=v1.x; in[5]=v1.y; in[6]=v1.z; in[7]=v1.w;
                        in[8]=v2.x; in[9]=v2.y; in[10]=v2.z; in[11]=v2.w;
                        in[12]=v3.x; in[13]=v3.y; in[14]=v3.z; in[15]=v3.w;
                    } else {
                        #pragma unroll
                        for (int i = 0; i < 16; i++) in[i] = 0.f;
                    }
                    u64 cw[5];
                    #pragma unroll
                    for (int d = 0; d < 5; d++)
                        cw[d] = (iy6 < 5)
                            ? *reinterpret_cast<const u64*>(&wch[(iy6*5 + d)*16 + c0]) : 0ull;
                    #pragma unroll
                    for (int d = 0; d < 5; d++) {
                        #pragma unroll
                        for (int j = 0; j < 8; j++) {
                            u64 x2 = dup2(in[j + d + 2]);
                            fma2(A0[j], x2, cw[d]);
                            fma2(A1[j], x2, pw[d]);
                        }
                    }
                    #pragma unroll
                    for (int d = 0; d < 5; d++) pw[d] = cw[d];
                }
            }
            float4 o0, o1;
            {
                float2 q0[8], q1[8];
                #pragma unroll
                for (int j = 0; j < 8; j++) { q0[j] = upk(A0[j]); q1[j] = upk(A1[j]); }
                o0.x = relu(fmaxf(fmaxf(q0[0].x,q0[1].x), fmaxf(q1[0].x,q1[1].x)));
                o0.y = relu(fmaxf(fmaxf(q0[2].x,q0[3].x), fmaxf(q1[2].x,q1[3].x)));
                o0.z = relu(fmaxf(fmaxf(q0[4].x,q0[5].x), fmaxf(q1[4].x,q1[5].x)));
                o0.w = relu(fmaxf(fmaxf(q0[6].x,q0[7].x), fmaxf(q1[6].x,q1[7].x)));
                o1.x = relu(fmaxf(fmaxf(q0[0].y,q0[1].y), fmaxf(q1[0].y,q1[1].y)));
                o1.y = relu(fmaxf(fmaxf(q0[2].y,q0[3].y), fmaxf(q1[2].y,q1[3].y)));
                o1.z = relu(fmaxf(fmaxf(q0[4].y,q0[5].y), fmaxf(q1[4].y,q1[5].y)));
                o1.w = relu(fmaxf(fmaxf(q0[6].y,q0[7].y), fmaxf(q1[6].y,q1[7].y)));
            }
            *reinterpret_cast<float4*>(
                &g_feat[b*FEAT_DIM + ((l*16 + c0)*16 + py)*16 + xg*4])     = o0;
            *reinterpret_cast<float4*>(
                &g_feat[b*FEAT_DIM + ((l*16 + c0 + 1)*16 + py)*16 + xg*4]) = o1;
        }
        __syncthreads();
    }
}

// ---- h = relu(feat @ lin_w + lin_b), f32x2 j-packed ----
__global__ __launch_bounds__(256)
void lin_kernel(const float* __restrict__ Wl, const float* __restrict__ bl)
{
    __shared__ __align__(16) float As[64][33];
    __shared__ __align__(16) float Bs[32][68];   // stride 68 -> conflict-free float4
    const int bn = blockIdx.x & 7;
    const int bm = blockIdx.x >> 3;
    const int t  = threadIdx.x;
    const int txg = t & 15, tyg = t >> 4;
    const int j0 = txg * 4, i0 = tyg * 4;
    const int rowBase = bm * 64, colBase = bn * 64;
    u64 acc2[4][2] = {};
    for (int kt = 0; kt < FEAT_DIM; kt += 32) {
        #pragma unroll
        for (int r = 0; r < 8; r++) {
            int idx = t + r*256;
            int row = idx >> 5, kk = idx & 31;
            As[row][kk] = g_feat[(rowBase + row)*FEAT_DIM + kt + kk];
        }
        #pragma unroll
        for (int r = 0; r < 8; r++) {
            int idx = t + r*256;
            int row = idx >> 6, col = idx & 63;
            Bs[row][col] = Wl[(kt + row)*512 + colBase + col];
        }
        __syncthreads();
        #pragma unroll
        for (int k = 0; k < 32; k++) {
            ulonglong2 bv = *reinterpret_cast<const ulonglong2*>(&Bs[k][j0]);
            #pragma unroll
            for (int r = 0; r < 4; r++) {
                u64 a2 = dup2(As[i0 + r][k]);
                fma2(acc2[r][0], a2, bv.x);
                fma2(acc2[r][1], a2, bv.y);
            }
        }
        __syncthreads();
    }
    #pragma unroll
    for (int r = 0; r < 4; r++) {
        float2 s0 = upk(acc2[r][0]);
        float2 s1 = upk(acc2[r][1]);
        float* op = &g_hid[(rowBase + i0 + r)*512 + colBase + j0];
        op[0] = relu(s0.x + bl[colBase + j0 + 0]);
        op[1] = relu(s0.y + bl[colBase + j0 + 1]);
        op[2] = relu(s1.x + bl[colBase + j0 + 2]);
        op[3] = relu(s1.y + bl[colBase + j0 + 3]);
    }
}

// ---- out = h @ score_w + score_b : one warp per row ----
__global__ __launch_bounds__(256)
void score_kernel(const float* __restrict__ sw, const float* __restrict__ sb,
                  float* __restrict__ out)
{
    int gw   = (blockIdx.x * blockDim.x + threadIdx.x) >> 5;
    int lane = threadIdx.x & 31;
    if (gw >= NB) return;
    const float* h = g_hid + gw * 512;
    float s = 0.f;
    #pragma unroll
    for (int j = lane; j < 512; j += 32) s += h[j] * sw[j];
    #pragma unroll
    for (int o = 16; o > 0; o >>= 1) s += __shfl_xor_sync(0xFFFFFFFFu, s, o);
    if (lane == 0) out[gw] = s + sb[0];
}

extern "C" void kernel_launch(void* const* d_in, const int* in_sizes, int n_in,
                              void* d_out, int out_size)
{
    const float* x_q  = (const float*)d_in[0];
    const float* x_c  = (const float*)d_in[1];
    const float* w0   = (const float*)d_in[2];
    const float* b0   = (const float*)d_in[3];
    const float* w1   = (const float*)d_in[4];
    const float* b1   = (const float*)d_in[5];
    const float* w2   = (const float*)d_in[6];
    const float* b2   = (const float*)d_in[7];
    const float* c1w  = (const float*)d_in[8];
    const float* c1b  = (const float*)d_in[9];
    const float* c2w  = (const float*)d_in[10];
    const float* c2b  = (const float*)d_in[11];
    const float* linw = (const float*)d_in[12];
    const float* linb = (const float*)d_in[13];
    const float* scw  = (const float*)d_in[14];
    const float* scb  = (const float*)d_in[15];
    const int*   eiq  = (const int*)d_in[16];
    const int*   eic  = (const int*)d_in[17];

    cudaFuncSetAttribute(fused_kernel, cudaFuncAttributeMaxDynamicSharedMemorySize, SMEM_BYTES);

    fused_kernel<<<NB, 512, SMEM_BYTES>>>(x_q, x_c, w0, b0, w1, b1, w2, b2,
                                          c1w, c1b, c2w, c2b, eiq, eic);
    lin_kernel<<<128, 256>>>(linw, linb);
    score_kernel<<<128, 256>>>(scw, scb, (float*)d_out);
}

// round 6
// speedup vs baseline: 2.5457x; 1.1187x over previous
#include <cuda_runtime.h>

#define NB 1024
#define NN 64
#define DD 128
#define NE 512
#define BE (NB*NE)
#define HS 132                 // padded smem row stride (float4-aligned)
#define HSZ (NN*HS)            // 8448 floats
#define SIMS_S 72              // 4 pad | 64 data | 4 pad
#define P1S 40                 // 4 pad | 32 data | 4 pad
#define FEAT_DIM 12288
#define KSLICE 6144            // FEAT_DIM / 2

typedef unsigned long long u64;

__device__ float g_feat[NB*FEAT_DIM];
__device__ float g_hid[NB*512];
__device__ float g_hid2[NB*512];

#define TAIL_WORDS 5962
#define SMEM_WORDS (4*HSZ + TAIL_WORDS)
#define SMEM_BYTES (SMEM_WORDS*4)

__device__ __forceinline__ float relu(float v) { return fmaxf(v, 0.f); }

__device__ __forceinline__ u64 dup2(float v) {
    u64 r; asm("mov.b64 %0, {%1, %1};" : "=l"(r) : "f"(v)); return r;
}
__device__ __forceinline__ float2 upk(u64 v) {
    float2 r; asm("mov.b64 {%0, %1}, %2;" : "=f"(r.x), "=f"(r.y) : "l"(v)); return r;
}
__device__ __forceinline__ void fma2(u64 &d, u64 a, u64 b) {
    asm("fma.rn.f32x2 %0, %1, %2, %0;" : "+l"(d) : "l"(a), "l"(b));
}

__global__ __launch_bounds__(512, 1)
void fused_kernel(const float* __restrict__ x_q, const float* __restrict__ x_c,
                  const float* __restrict__ w0, const float* __restrict__ b0,
                  const float* __restrict__ w1, const float* __restrict__ b1,
                  const float* __restrict__ w2, const float* __restrict__ b2,
                  const float* __restrict__ c1w, const float* __restrict__ c1b,
                  const float* __restrict__ c2w, const float* __restrict__ c2b,
                  const int* __restrict__ eiq, const int* __restrict__ eic)
{
    extern __shared__ __align__(16) float sm[];
    float* Hq = sm;
    float* Hc = Hq + HSZ;
    float* Mq = Hc + HSZ;
    float* Mc = Mq + HSZ;
    float* sims = Mq;                 // 64*72 = 4608
    float* p1   = Mq + 4608;          // 8*32*40 = 10240
    float* tail = sm + 4*HSZ;
    int*   off_q = (int*)tail;        // 65
    int*   off_c = off_q + 65;        // 65
    int*   cntq  = off_c + 65;        // 64
    int*   cntc  = cntq + 64;         // 64
    int*   curq  = cntc + 64;         // 64
    int*   curc  = curq + 64;         // 64
    int*   csq   = curc + 64;         // 512
    int*   csc   = csq + 512;         // 512
    float* cnq   = (float*)(csc + 512); // 512
    float* cnc   = cnq + 512;         // 512
    float* disq  = cnc + 512;         // 64
    float* disc  = disq + 64;         // 64
    float* w1t   = disc + 64;         // 200  : [(dy*5+dx)*8 + c]
    float* w2t   = w1t + 200;         // 3200 : [((ci*5+dy)*5+dx)*16 + c]

    const int b    = blockIdx.x;
    const int t    = threadIdx.x;
    const int base = b * NN;

    // ---- load node features, vectorized ----
    for (int idx = t; idx < NN*DD/4; idx += 512) {
        int i = idx >> 5, k4 = (idx & 31) * 4;
        *reinterpret_cast<float4*>(&Hq[i*HS + k4]) =
            *reinterpret_cast<const float4*>(&x_q[(base + i)*DD + k4]);
        *reinterpret_cast<float4*>(&Hc[i*HS + k4]) =
            *reinterpret_cast<const float4*>(&x_c[(base + i)*DD + k4]);
    }
    if (t < 64) { cntq[t] = 0; cntc[t] = 0; }
    __syncthreads();

    // ---- edges: degree count; stage packed (s,d) in dead M region ----
    int* tq = (int*)Mq;
    int* tc = (int*)Mc;
    if (t < NE) {
        int e = b*NE + t;
        int s = eiq[e] - base, d = eiq[BE + e] - base;
        tq[t] = (s << 8) | d;
        atomicAdd(&cntq[d], 1);
        s = eic[e] - base; d = eic[BE + e] - base;
        tc[t] = (s << 8) | d;
        atomicAdd(&cntc[d], 1);
    }
    __syncthreads();
    if (t < 64)        disq[t]      = rsqrtf((float)cntq[t] + 1.0f);
    else if (t < 128)  disc[t - 64] = rsqrtf((float)cntc[t - 64] + 1.0f);
    if (t == 0)  { int a = 0; for (int i = 0; i < 64; i++){ off_q[i] = a; a += cntq[i]; } off_q[64] = a; }
    if (t == 32) { int a = 0; for (int i = 0; i < 64; i++){ off_c[i] = a; a += cntc[i]; } off_c[64] = a; }
    __syncthreads();
    if (t < 64) { curq[t] = off_q[t]; curc[t] = off_c[t]; }
    __syncthreads();
    if (t < NE) {
        int sd = tq[t]; int s = sd >> 8, d = sd & 255;
        int p = atomicAdd(&curq[d], 1);
        csq[p] = s; cnq[p] = disq[s] * disq[d];
        sd = tc[t]; s = sd >> 8; d = sd & 255;
        p = atomicAdd(&curc[d], 1);
        csc[p] = s; cnc[p] = disc[s] * disc[d];
    }
    __syncthreads();

    for (int l = 0; l < 3; l++) {
        const float* W  = (l == 0) ? w0 : (l == 1) ? w1 : w2;
        const float* bb = (l == 0) ? b0 : (l == 1) ? b1 : b2;

        // ---- GEMM: M = (relu?)(H) @ W, f32x2 j-packed ----
        {
            const int j0 = (t & 31) * 4, i0 = (t >> 5) * 4;
            u64 aq2[4][2] = {}, ac2[4][2] = {};
            for (int k = 0; k < DD; k += 4) {
                float4 hq[4], hc[4];
                #pragma unroll
                for (int r = 0; r < 4; r++) {
                    hq[r] = *reinterpret_cast<const float4*>(&Hq[(i0 + r)*HS + k]);
                    hc[r] = *reinterpret_cast<const float4*>(&Hc[(i0 + r)*HS + k]);
                    if (l) {
                        hq[r].x = relu(hq[r].x); hq[r].y = relu(hq[r].y);
                        hq[r].z = relu(hq[r].z); hq[r].w = relu(hq[r].w);
                        hc[r].x = relu(hc[r].x); hc[r].y = relu(hc[r].y);
                        hc[r].z = relu(hc[r].z); hc[r].w = relu(hc[r].w);
                    }
                }
                #pragma unroll
                for (int kk = 0; kk < 4; kk++) {
                    ulonglong2 wv = *reinterpret_cast<const ulonglong2*>(W + (k + kk)*DD + j0);
                    #pragma unroll
                    for (int r = 0; r < 4; r++) {
                        float aqv = kk == 0 ? hq[r].x : kk == 1 ? hq[r].y : kk == 2 ? hq[r].z : hq[r].w;
                        u64 ad = dup2(aqv);
                        fma2(aq2[r][0], ad, wv.x);
                        fma2(aq2[r][1], ad, wv.y);
                        float acv = kk == 0 ? hc[r].x : kk == 1 ? hc[r].y : kk == 2 ? hc[r].z : hc[r].w;
                        u64 cd = dup2(acv);
                        fma2(ac2[r][0], cd, wv.x);
                        fma2(ac2[r][1], cd, wv.y);
                    }
                }
            }
            #pragma unroll
            for (int r = 0; r < 4; r++) {
                ulonglong2 sq; sq.x = aq2[r][0]; sq.y = aq2[r][1];
                ulonglong2 sc; sc.x = ac2[r][0]; sc.y = ac2[r][1];
                *reinterpret_cast<ulonglong2*>(&Mq[(i0 + r)*HS + j0]) = sq;
                *reinterpret_cast<ulonglong2*>(&Mc[(i0 + r)*HS + j0]) = sc;
            }
        }
        __syncthreads();

        // ---- aggregate via CSR, feature pairs (u64) ----
        {
            const int f2 = (t & 63) * 2, g = t >> 6;   // g in 0..7
            u64 bf2 = *reinterpret_cast<const u64*>(&bb[f2]);
            #pragma unroll 1
            for (int r = 0; r < 8; r++) {
                int i = g + (r << 3);
                u64 acc = bf2;
                fma2(acc, dup2(disq[i]*disq[i]), *reinterpret_cast<const u64*>(&Mq[i*HS + f2]));
                int e0 = off_q[i], e1 = off_q[i + 1];
                for (int p = e0; p < e1; p++)
                    fma2(acc, dup2(cnq[p]), *reinterpret_cast<const u64*>(&Mq[csq[p]*HS + f2]));
                *reinterpret_cast<u64*>(&Hq[i*HS + f2]) = acc;
                acc = bf2;
                fma2(acc, dup2(disc[i]*disc[i]), *reinterpret_cast<const u64*>(&Mc[i*HS + f2]));
                e0 = off_c[i]; e1 = off_c[i + 1];
                for (int p = e0; p < e1; p++)
                    fma2(acc, dup2(cnc[p]), *reinterpret_cast<const u64*>(&Mc[csc[p]*HS + f2]));
                *reinterpret_cast<u64*>(&Hc[i*HS + f2]) = acc;
            }
        }
        __syncthreads();

        // ---- sims = out_q @ out_c^T, f32x2 k-packed ----
        {
            const int j = t & 31, ig = t >> 5;
            u64 a2[4][2] = {};
            for (int k = 0; k < DD; k += 4) {
                ulonglong2 ca = *reinterpret_cast<const ulonglong2*>(&Hc[j*HS + k]);
                ulonglong2 cb = *reinterpret_cast<const ulonglong2*>(&Hc[(j + 32)*HS + k]);
                #pragma unroll
                for (int r = 0; r < 4; r++) {
                    ulonglong2 qv = *reinterpret_cast<const ulonglong2*>(&Hq[(ig*4 + r)*HS + k]);
                    fma2(a2[r][0], qv.x, ca.x);
                    fma2(a2[r][0], qv.y, ca.y);
                    fma2(a2[r][1], qv.x, cb.x);
                    fma2(a2[r][1], qv.y, cb.y);
                }
            }
            #pragma unroll
            for (int r = 0; r < 4; r++) {
                float2 s0 = upk(a2[r][0]);
                float2 s1 = upk(a2[r][1]);
                sims[(ig*4 + r)*SIMS_S + 4 + j]      = s0.x + s0.y;
                sims[(ig*4 + r)*SIMS_S + 4 + j + 32] = s1.x + s1.y;
            }
        }
        // zero the column pads of sims and p1
        for (int idx = t; idx < 2560; idx += 512) {
            if (idx < 512) {
                int row = idx >> 3, pc = idx & 7;
                sims[row*SIMS_S + (pc < 4 ? pc : pc + 64)] = 0.f;
            } else {
                int k2 = idx - 512;
                int row = k2 >> 3, pc = k2 & 7;
                p1[row*P1S + (pc < 4 ? pc : pc + 32)] = 0.f;
            }
        }
        // stage conv weights, channel-transposed
        for (int idx = t; idx < 200; idx += 512) {
            int c = idx & 7, rest = idx >> 3;
            w1t[idx] = c1w[l*200 + c*25 + rest];
        }
        for (int idx = t; idx < 3200; idx += 512) {
            int c = idx & 15, rest = idx >> 4;
            int dxx = rest % 5, r2 = rest / 5;
            int dyy = r2 % 5, ci = r2 / 5;
            w2t[idx] = c2w[l*3200 + (c*8 + ci)*25 + dyy*5 + dxx];
        }
        __syncthreads();

        // ---- conv1 (1->8,5x5,pad2)+relu+pool2, channel-pair f32x2 ----
        #pragma unroll 1
        for (int it = 0; it < 2; it++) {
            int item = it*512 + t;
            int xg = item & 7, py = (item >> 3) & 31, cp = item >> 8;
            int Xc = xg * 8, Y = py * 2;
            int c0 = cp * 2;
            u64 bias2 = *reinterpret_cast<const u64*>(&c1b[l*8 + c0]);
            u64 A0[8], A1[8];
            #pragma unroll
            for (int j = 0; j < 8; j++) { A0[j] = bias2; A1[j] = bias2; }
            u64 pw[5];
            #pragma unroll
            for (int d = 0; d < 5; d++) pw[d] = 0;
            #pragma unroll
            for (int iy6 = 0; iy6 < 6; iy6++) {
                int iy = Y - 2 + iy6;
                float in[16];
                if ((unsigned)iy < 64u) {
                    const float* rp = &sims[iy*SIMS_S + Xc];
                    float4 v0 = *reinterpret_cast<const float4*>(rp);
                    float4 v1 = *reinterpret_cast<const float4*>(rp + 4);
                    float4 v2 = *reinterpret_cast<const float4*>(rp + 8);
                    float4 v3 = *reinterpret_cast<const float4*>(rp + 12);
                    in[0]=v0.x; in[1]=v0.y; in[2]=v0.z; in[3]=v0.w;
                    in[4]=v1.x; in[5]=v1.y; in[6]=v1.z; in[7]=v1.w;
                    in[8]=v2.x; in[9]=v2.y; in[10]=v2.z; in[11]=v2.w;
                    in[12]=v3.x; in[13]=v3.y; in[14]=v3.z; in[15]=v3.w;
                } else {
                    #pragma unroll
                    for (int i = 0; i < 16; i++) in[i] = 0.f;
                }
                u64 cw[5];
                #pragma unroll
                for (int d = 0; d < 5; d++)
                    cw[d] = (iy6 < 5)
                        ? *reinterpret_cast<const u64*>(&w1t[(iy6*5 + d)*8 + c0]) : 0ull;
                #pragma unroll
                for (int d = 0; d < 5; d++) {
                    #pragma unroll
                    for (int j = 0; j < 8; j++) {
                        u64 x2 = dup2(in[j + d + 2]);
                        fma2(A0[j], x2, cw[d]);
                        fma2(A1[j], x2, pw[d]);
                    }
                }
                #pragma unroll
                for (int d = 0; d < 5; d++) pw[d] = cw[d];
            }
            float4 o0, o1;
            {
                float2 q0[8], q1[8];
                #pragma unroll
                for (int j = 0; j < 8; j++) { q0[j] = upk(A0[j]); q1[j] = upk(A1[j]); }
                o0.x = relu(fmaxf(fmaxf(q0[0].x,q0[1].x), fmaxf(q1[0].x,q1[1].x)));
                o0.y = relu(fmaxf(fmaxf(q0[2].x,q0[3].x), fmaxf(q1[2].x,q1[3].x)));
                o0.z = relu(fmaxf(fmaxf(q0[4].x,q0[5].x), fmaxf(q1[4].x,q1[5].x)));
                o0.w = relu(fmaxf(fmaxf(q0[6].x,q0[7].x), fmaxf(q1[6].x,q1[7].x)));
                o1.x = relu(fmaxf(fmaxf(q0[0].y,q0[1].y), fmaxf(q1[0].y,q1[1].y)));
                o1.y = relu(fmaxf(fmaxf(q0[2].y,q0[3].y), fmaxf(q1[2].y,q1[3].y)));
                o1.z = relu(fmaxf(fmaxf(q0[4].y,q0[5].y), fmaxf(q1[4].y,q1[5].y)));
                o1.w = relu(fmaxf(fmaxf(q0[6].y,q0[7].y), fmaxf(q1[6].y,q1[7].y)));
            }
            *reinterpret_cast<float4*>(&p1[(c0*32 + py)*P1S + 4 + xg*4])     = o0;
            *reinterpret_cast<float4*>(&p1[((c0+1)*32 + py)*P1S + 4 + xg*4]) = o1;
        }
        __syncthreads();

        // ---- conv2 (8->16,5x5,pad2)+relu+pool2, channel-pair f32x2 ----
        {
            int xg = t & 3, py = (t >> 2) & 15, cp = t >> 6;
            int Xc = xg * 8, Y = py * 2;
            int c0 = cp * 2;
            u64 bias2 = *reinterpret_cast<const u64*>(&c2b[l*16 + c0]);
            u64 A0[8], A1[8];
            #pragma unroll
            for (int j = 0; j < 8; j++) { A0[j] = bias2; A1[j] = bias2; }
            #pragma unroll 1
            for (int ci = 0; ci < 8; ci++) {
                const float* pch = p1 + ci*32*P1S;
                const float* wch = w2t + ci*400;
                u64 pw[5];
                #pragma unroll
                for (int d = 0; d < 5; d++) pw[d] = 0;
                #pragma unroll
                for (int iy6 = 0; iy6 < 6; iy6++) {
                    int iy = Y - 2 + iy6;
                    float in[16];
                    if ((unsigned)iy < 32u) {
                        const float* rp = pch + iy*P1S + Xc;
                        float4 v0 = *reinterpret_cast<const float4*>(rp);
                        float4 v1 = *reinterpret_cast<const float4*>(rp + 4);
                        float4 v2 = *reinterpret_cast<const float4*>(rp + 8);
                        float4 v3 = *reinterpret_cast<const float4*>(rp + 12);
                        in[0]=v0.x; in[1]=v0.y; in[2]=v0.z; in[3]=v0.w;
                        in[4]=v1.x; in[5]=v1.y; in[6]=v1.z; in[7]=v1.w;
                        in[8]=v2.x; in[9]=v2.y; in[10]=v2.z; in[11]=v2.w;
                        in[12]=v3.x; in[13]=v3.y; in[14]=v3.z; in[15]=v3.w;
                    } else {
                        #pragma unroll
                        for (int i = 0; i < 16; i++) in[i] = 0.f;
                    }
                    u64 cw[5];
                    #pragma unroll
                    for (int d = 0; d < 5; d++)
                        cw[d] = (iy6 < 5)
                            ? *reinterpret_cast<const u64*>(&wch[(iy6*5 + d)*16 + c0]) : 0ull;
                    #pragma unroll
                    for (int d = 0; d < 5; d++) {
                        #pragma unroll
                        for (int j = 0; j < 8; j++) {
                            u64 x2 = dup2(in[j + d + 2]);
                            fma2(A0[j], x2, cw[d]);
                            fma2(A1[j], x2, pw[d]);
                        }
                    }
                    #pragma unroll
                    for (int d = 0; d < 5; d++) pw[d] = cw[d];
                }
            }
            float4 o0, o1;
            {
                float2 q0[8], q1[8];
                #pragma unroll
                for (int j = 0; j < 8; j++) { q0[j] = upk(A0[j]); q1[j] = upk(A1[j]); }
                o0.x = relu(fmaxf(fmaxf(q0[0].x,q0[1].x), fmaxf(q1[0].x,q1[1].x)));
                o0.y = relu(fmaxf(fmaxf(q0[2].x,q0[3].x), fmaxf(q1[2].x,q1[3].x)));
                o0.z = relu(fmaxf(fmaxf(q0[4].x,q0[5].x), fmaxf(q1[4].x,q1[5].x)));
                o0.w = relu(fmaxf(fmaxf(q0[6].x,q0[7].x), fmaxf(q1[6].x,q1[7].x)));
                o1.x = relu(fmaxf(fmaxf(q0[0].y,q0[1].y), fmaxf(q1[0].y,q1[1].y)));
                o1.y = relu(fmaxf(fmaxf(q0[2].y,q0[3].y), fmaxf(q1[2].y,q1[3].y)));
                o1.z = relu(fmaxf(fmaxf(q0[4].y,q0[5].y), fmaxf(q1[4].y,q1[5].y)));
                o1.w = relu(fmaxf(fmaxf(q0[6].y,q0[7].y), fmaxf(q1[6].y,q1[7].y)));
            }
            *reinterpret_cast<float4*>(
                &g_feat[b*FEAT_DIM + ((l*16 + c0)*16 + py)*16 + xg*4])     = o0;
            *reinterpret_cast<float4*>(
                &g_feat[b*FEAT_DIM + ((l*16 + c0 + 1)*16 + py)*16 + xg*4]) = o1;
        }
        __syncthreads();
    }
}

// ---- partial = feat @ lin_w (K slice) : 2 slices, 2 CTAs/SM ----
__global__ __launch_bounds__(256, 2)
void lin_kernel(const float* __restrict__ Wl)
{
    __shared__ __align__(16) float As[64][36];   // stride 36: float4-aligned
    __shared__ __align__(16) float Bs[32][68];   // stride 68: conflict-free float4
    const int blk   = blockIdx.x & 127;
    const int slice = blockIdx.x >> 7;           // 0 or 1
    const int bn = blk & 7;
    const int bm = blk >> 3;
    const int t  = threadIdx.x;
    const int txg = t & 15, tyg = t >> 4;
    const int j0 = txg * 4, i0 = tyg * 4;
    const int rowBase = bm * 64, colBase = bn * 64;
    const int kBase = slice * KSLICE;
    float* out = slice ? g_hid2 : g_hid;

    u64 acc2[4][2] = {};
    for (int kt = kBase; kt < kBase + KSLICE; kt += 32) {
        #pragma unroll
        for (int r = 0; r < 8; r++) {
            int idx = t + r*256;
            int row = idx >> 5, kk = idx & 31;
            As[row][kk] = g_feat[(rowBase + row)*FEAT_DIM + kt + kk];
        }
        #pragma unroll
        for (int r = 0; r < 8; r++) {
            int idx = t + r*256;
            int row = idx >> 6, col = idx & 63;
            Bs[row][col] = Wl[(kt + row)*512 + colBase + col];
        }
        __syncthreads();
        #pragma unroll
        for (int k = 0; k < 32; k += 4) {
            float4 av[4];
            #pragma unroll
            for (int r = 0; r < 4; r++)
                av[r] = *reinterpret_cast<const float4*>(&As[i0 + r][k]);
            #pragma unroll
            for (int kk = 0; kk < 4; kk++) {
                ulonglong2 bv = *reinterpret_cast<const ulonglong2*>(&Bs[k + kk][j0]);
                #pragma unroll
                for (int r = 0; r < 4; r++) {
                    float a = kk == 0 ? av[r].x : kk == 1 ? av[r].y : kk == 2 ? av[r].z : av[r].w;
                    u64 a2 = dup2(a);
                    fma2(acc2[r][0], a2, bv.x);
                    fma2(acc2[r][1], a2, bv.y);
                }
            }
        }
        __syncthreads();
    }
    #pragma unroll
    for (int r = 0; r < 4; r++) {
        ulonglong2 s; s.x = acc2[r][0]; s.y = acc2[r][1];
        *reinterpret_cast<ulonglong2*>(
            &out[(rowBase + i0 + r)*512 + colBase + j0]) = s;
    }
}

// ---- out = relu(p1+p2+lin_b) @ score_w + score_b : one warp per row ----
__global__ __launch_bounds__(256)
void score_kernel(const float* __restrict__ bl,
                  const float* __restrict__ sw, const float* __restrict__ sb,
                  float* __restrict__ out)
{
    int gw   = (blockIdx.x * blockDim.x + threadIdx.x) >> 5;
    int lane = threadIdx.x & 31;
    if (gw >= NB) return;
    const float* h1 = g_hid  + gw * 512;
    const float* h2 = g_hid2 + gw * 512;
    float s = 0.f;
    #pragma unroll
    for (int j = lane; j < 512; j += 32)
        s += relu(h1[j] + h2[j] + bl[j]) * sw[j];
    #pragma unroll
    for (int o = 16; o > 0; o >>= 1) s += __shfl_xor_sync(0xFFFFFFFFu, s, o);
    if (lane == 0) out[gw] = s + sb[0];
}

extern "C" void kernel_launch(void* const* d_in, const int* in_sizes, int n_in,
                              void* d_out, int out_size)
{
    const float* x_q  = (const float*)d_in[0];
    const float* x_c  = (const float*)d_in[1];
    const float* w0   = (const float*)d_in[2];
    const float* b0   = (const float*)d_in[3];
    const float* w1   = (const float*)d_in[4];
    const float* b1   = (const float*)d_in[5];
    const float* w2   = (const float*)d_in[6];
    const float* b2   = (const float*)d_in[7];
    const float* c1w  = (const float*)d_in[8];
    const float* c1b  = (const float*)d_in[9];
    const float* c2w  = (const float*)d_in[10];
    const float* c2b  = (const float*)d_in[11];
    const float* linw = (const float*)d_in[12];
    const float* linb = (const float*)d_in[13];
    const float* scw  = (const float*)d_in[14];
    const float* scb  = (const float*)d_in[15];
    const int*   eiq  = (const int*)d_in[16];
    const int*   eic  = (const int*)d_in[17];

    cudaFuncSetAttribute(fused_kernel, cudaFuncAttributeMaxDynamicSharedMemorySize, SMEM_BYTES);

    fused_kernel<<<NB, 512, SMEM_BYTES>>>(x_q, x_c, w0, b0, w1, b1, w2, b2,
                                          c1w, c1b, c2w, c2b, eiq, eic);
    lin_kernel<<<256, 256>>>(linw);
    score_kernel<<<128, 256>>>(linb, scw, scb, (float*)d_out);
}

// round 7
// speedup vs baseline: 2.7258x; 1.0707x over previous
#include <cuda_runtime.h>

#define NB 1024
#define NN 64
#define DD 128
#define NE 512
#define BE (NB*NE)
#define HS 132                 // padded smem row stride (float4-aligned)
#define HSZ (NN*HS)            // 8448 floats
#define SIMS_S 76              // 4 pad | 64 data | 8 pad ; 76/4=19 ≡ 3 (mod 8)
#define P1S 44                 // 4 pad | 32 data | 8 pad ; 44/4=11 ≡ 3 (mod 8)
#define P1PLANE (32*P1S)       // 1408
#define FEAT_DIM 12288
#define KS4 3072               // FEAT_DIM/4

typedef unsigned long long u64;

__device__ float g_feat[NB*FEAT_DIM];
__device__ float g_hidp[4][NB*512];

#define TAIL_WORDS 5962
#define SMEM_WORDS (4*HSZ + TAIL_WORDS)
#define SMEM_BYTES (SMEM_WORDS*4)

__device__ __forceinline__ float relu(float v) { return fmaxf(v, 0.f); }

__device__ __forceinline__ u64 dup2(float v) {
    u64 r; asm("mov.b64 %0, {%1, %1};" : "=l"(r) : "f"(v)); return r;
}
__device__ __forceinline__ float2 upk(u64 v) {
    float2 r; asm("mov.b64 {%0, %1}, %2;" : "=f"(r.x), "=f"(r.y) : "l"(v)); return r;
}
__device__ __forceinline__ void fma2(u64 &d, u64 a, u64 b) {
    asm("fma.rn.f32x2 %0, %1, %2, %0;" : "+l"(d) : "l"(a), "l"(b));
}
// pair-interleaved row permutations (conflict-free strided access)
__device__ __forceinline__ int srow(int r) { return (r >> 1) + ((r & 1) << 5); }  // 64 rows
__device__ __forceinline__ int prow(int r) { return (r >> 1) + ((r & 1) << 4); }  // 32 rows

__global__ __launch_bounds__(512, 1)
void fused_kernel(const float* __restrict__ x_q, const float* __restrict__ x_c,
                  const float* __restrict__ w0, const float* __restrict__ b0,
                  const float* __restrict__ w1, const float* __restrict__ b1,
                  const float* __restrict__ w2, const float* __restrict__ b2,
                  const float* __restrict__ c1w, const float* __restrict__ c1b,
                  const float* __restrict__ c2w, const float* __restrict__ c2b,
                  const int* __restrict__ eiq, const int* __restrict__ eic)
{
    extern __shared__ __align__(16) float sm[];
    float* Hq = sm;
    float* Hc = Hq + HSZ;
    float* Mq = Hc + HSZ;
    float* Mc = Mq + HSZ;
    float* sims = Mq;                 // 64*76 = 4864
    float* p1   = Mq + 4864;          // 8*32*44 = 11264 (ends 16128 <= 16896)
    float* tail = sm + 4*HSZ;
    int*   off_q = (int*)tail;        // 65
    int*   off_c = off_q + 65;        // 65
    int*   cntq  = off_c + 65;        // 64
    int*   cntc  = cntq + 64;         // 64
    int*   curq  = cntc + 64;         // 64
    int*   curc  = curq + 64;         // 64
    int*   csq   = curc + 64;         // 512
    int*   csc   = csq + 512;         // 512
    float* cnq   = (float*)(csc + 512); // 512
    float* cnc   = cnq + 512;         // 512
    float* disq  = cnc + 512;         // 64
    float* disc  = disq + 64;         // 64
    float* w1t   = disc + 64;         // 200  : [(dy*5+dx)*8 + c]
    float* w2t   = w1t + 200;         // 3200 : [((ci*5+dy)*5+dx)*16 + c]

    const int b    = blockIdx.x;
    const int t    = threadIdx.x;
    const int base = b * NN;

    // ---- load node features, vectorized ----
    for (int idx = t; idx < NN*DD/4; idx += 512) {
        int i = idx >> 5, k4 = (idx & 31) * 4;
        *reinterpret_cast<float4*>(&Hq[i*HS + k4]) =
            *reinterpret_cast<const float4*>(&x_q[(base + i)*DD + k4]);
        *reinterpret_cast<float4*>(&Hc[i*HS + k4]) =
            *reinterpret_cast<const float4*>(&x_c[(base + i)*DD + k4]);
    }
    if (t < 64) { cntq[t] = 0; cntc[t] = 0; }
    __syncthreads();

    // ---- edges: degree count; stage packed (s,d) in dead M region ----
    int* tq = (int*)Mq;
    int* tc = (int*)Mc;
    if (t < NE) {
        int e = b*NE + t;
        int s = eiq[e] - base, d = eiq[BE + e] - base;
        tq[t] = (s << 8) | d;
        atomicAdd(&cntq[d], 1);
        s = eic[e] - base; d = eic[BE + e] - base;
        tc[t] = (s << 8) | d;
        atomicAdd(&cntc[d], 1);
    }
    __syncthreads();
    if (t < 64)        disq[t]      = rsqrtf((float)cntq[t] + 1.0f);
    else if (t < 128)  disc[t - 64] = rsqrtf((float)cntc[t - 64] + 1.0f);
    if (t == 0)  { int a = 0; for (int i = 0; i < 64; i++){ off_q[i] = a; a += cntq[i]; } off_q[64] = a; }
    if (t == 32) { int a = 0; for (int i = 0; i < 64; i++){ off_c[i] = a; a += cntc[i]; } off_c[64] = a; }
    __syncthreads();
    if (t < 64) { curq[t] = off_q[t]; curc[t] = off_c[t]; }
    __syncthreads();
    if (t < NE) {
        int sd = tq[t]; int s = sd >> 8, d = sd & 255;
        int p = atomicAdd(&curq[d], 1);
        csq[p] = s; cnq[p] = disq[s] * disq[d];
        sd = tc[t]; s = sd >> 8; d = sd & 255;
        p = atomicAdd(&curc[d], 1);
        csc[p] = s; cnc[p] = disc[s] * disc[d];
    }
    __syncthreads();

    for (int l = 0; l < 3; l++) {
        const float* W  = (l == 0) ? w0 : (l == 1) ? w1 : w2;
        const float* bb = (l == 0) ? b0 : (l == 1) ? b1 : b2;

        // ---- GEMM: M = (relu?)(H) @ W, f32x2 j-packed ----
        {
            const int j0 = (t & 31) * 4, i0 = (t >> 5) * 4;
            u64 aq2[4][2] = {}, ac2[4][2] = {};
            for (int k = 0; k < DD; k += 4) {
                float4 hq[4], hc[4];
                #pragma unroll
                for (int r = 0; r < 4; r++) {
                    hq[r] = *reinterpret_cast<const float4*>(&Hq[(i0 + r)*HS + k]);
                    hc[r] = *reinterpret_cast<const float4*>(&Hc[(i0 + r)*HS + k]);
                    if (l) {
                        hq[r].x = relu(hq[r].x); hq[r].y = relu(hq[r].y);
                        hq[r].z = relu(hq[r].z); hq[r].w = relu(hq[r].w);
                        hc[r].x = relu(hc[r].x); hc[r].y = relu(hc[r].y);
                        hc[r].z = relu(hc[r].z); hc[r].w = relu(hc[r].w);
                    }
                }
                #pragma unroll
                for (int kk = 0; kk < 4; kk++) {
                    ulonglong2 wv = *reinterpret_cast<const ulonglong2*>(W + (k + kk)*DD + j0);
                    #pragma unroll
                    for (int r = 0; r < 4; r++) {
                        float aqv = kk == 0 ? hq[r].x : kk == 1 ? hq[r].y : kk == 2 ? hq[r].z : hq[r].w;
                        u64 ad = dup2(aqv);
                        fma2(aq2[r][0], ad, wv.x);
                        fma2(aq2[r][1], ad, wv.y);
                        float acv = kk == 0 ? hc[r].x : kk == 1 ? hc[r].y : kk == 2 ? hc[r].z : hc[r].w;
                        u64 cd = dup2(acv);
                        fma2(ac2[r][0], cd, wv.x);
                        fma2(ac2[r][1], cd, wv.y);
                    }
                }
            }
            #pragma unroll
            for (int r = 0; r < 4; r++) {
                ulonglong2 sq; sq.x = aq2[r][0]; sq.y = aq2[r][1];
                ulonglong2 sc; sc.x = ac2[r][0]; sc.y = ac2[r][1];
                *reinterpret_cast<ulonglong2*>(&Mq[(i0 + r)*HS + j0]) = sq;
                *reinterpret_cast<ulonglong2*>(&Mc[(i0 + r)*HS + j0]) = sc;
            }
        }
        __syncthreads();

        // ---- aggregate via CSR, feature pairs (u64) ----
        {
            const int f2 = (t & 63) * 2, g = t >> 6;   // g in 0..7
            u64 bf2 = *reinterpret_cast<const u64*>(&bb[f2]);
            #pragma unroll 1
            for (int r = 0; r < 8; r++) {
                int i = g + (r << 3);
                u64 acc = bf2;
                fma2(acc, dup2(disq[i]*disq[i]), *reinterpret_cast<const u64*>(&Mq[i*HS + f2]));
                int e0 = off_q[i], e1 = off_q[i + 1];
                for (int p = e0; p < e1; p++)
                    fma2(acc, dup2(cnq[p]), *reinterpret_cast<const u64*>(&Mq[csq[p]*HS + f2]));
                *reinterpret_cast<u64*>(&Hq[i*HS + f2]) = acc;
                acc = bf2;
                fma2(acc, dup2(disc[i]*disc[i]), *reinterpret_cast<const u64*>(&Mc[i*HS + f2]));
                e0 = off_c[i]; e1 = off_c[i + 1];
                for (int p = e0; p < e1; p++)
                    fma2(acc, dup2(cnc[p]), *reinterpret_cast<const u64*>(&Mc[csc[p]*HS + f2]));
                *reinterpret_cast<u64*>(&Hc[i*HS + f2]) = acc;
            }
        }
        __syncthreads();

        // ---- sims = out_q @ out_c^T, f32x2 k-packed ; perm-row stores ----
        {
            const int j = t & 31, ig = t >> 5;
            u64 a2[4][2] = {};
            for (int k = 0; k < DD; k += 4) {
                ulonglong2 ca = *reinterpret_cast<const ulonglong2*>(&Hc[j*HS + k]);
                ulonglong2 cb = *reinterpret_cast<const ulonglong2*>(&Hc[(j + 32)*HS + k]);
                #pragma unroll
                for (int r = 0; r < 4; r++) {
                    ulonglong2 qv = *reinterpret_cast<const ulonglong2*>(&Hq[(ig*4 + r)*HS + k]);
                    fma2(a2[r][0], qv.x, ca.x);
                    fma2(a2[r][0], qv.y, ca.y);
                    fma2(a2[r][1], qv.x, cb.x);
                    fma2(a2[r][1], qv.y, cb.y);
                }
            }
            #pragma unroll
            for (int r = 0; r < 4; r++) {
                float2 s0 = upk(a2[r][0]);
                float2 s1 = upk(a2[r][1]);
                int sr = srow(ig*4 + r);
                sims[sr*SIMS_S + 4 + j]      = s0.x + s0.y;
                sims[sr*SIMS_S + 4 + j + 32] = s1.x + s1.y;
            }
        }
        // zero pads: sims (cols 0-3, 68-75), p1 (cols 0-3, 36-43)
        {
            float4 z4 = make_float4(0.f, 0.f, 0.f, 0.f);
            if (t < 64) {
                float* rp = &sims[t*SIMS_S];
                *reinterpret_cast<float4*>(rp)      = z4;
                *reinterpret_cast<float4*>(rp + 68) = z4;
                *reinterpret_cast<float4*>(rp + 72) = z4;
            } else if (t < 320) {
                int s = t - 64;
                float* rp = &p1[(s >> 5)*P1PLANE + (s & 31)*P1S];
                *reinterpret_cast<float4*>(rp)      = z4;
                *reinterpret_cast<float4*>(rp + 36) = z4;
                *reinterpret_cast<float4*>(rp + 40) = z4;
            }
        }
        // stage conv weights, channel-transposed
        for (int idx = t; idx < 200; idx += 512) {
            int c = idx & 7, rest = idx >> 3;
            w1t[idx] = c1w[l*200 + c*25 + rest];
        }
        for (int idx = t; idx < 3200; idx += 512) {
            int c = idx & 15, rest = idx >> 4;
            int dxx = rest % 5, r2 = rest / 5;
            int dyy = r2 % 5, ci = r2 / 5;
            w2t[idx] = c2w[l*3200 + (c*8 + ci)*25 + dyy*5 + dxx];
        }
        __syncthreads();

        // ---- conv1 (1->8,5x5,pad2)+relu+pool2 ; py fastest, perm rows ----
        #pragma unroll 1
        for (int it = 0; it < 2; it++) {
            int item = it*512 + t;
            int py = item & 31, xg = (item >> 5) & 7, cp = item >> 8;
            int Xc = xg * 8, Y = py * 2;
            int c0 = cp * 2;
            u64 bias2 = *reinterpret_cast<const u64*>(&c1b[l*8 + c0]);
            u64 A0[8], A1[8];
            #pragma unroll
            for (int j = 0; j < 8; j++) { A0[j] = bias2; A1[j] = bias2; }
            u64 pw[5];
            #pragma unroll
            for (int d = 0; d < 5; d++) pw[d] = 0;
            #pragma unroll
            for (int iy6 = 0; iy6 < 6; iy6++) {
                int iy = Y - 2 + iy6;
                float in[16];
                if ((unsigned)iy < 64u) {
                    const float* rp = &sims[srow(iy)*SIMS_S + Xc];
                    float4 v0 = *reinterpret_cast<const float4*>(rp);
                    float4 v1 = *reinterpret_cast<const float4*>(rp + 4);
                    float4 v2 = *reinterpret_cast<const float4*>(rp + 8);
                    float4 v3 = *reinterpret_cast<const float4*>(rp + 12);
                    in[0]=v0.x; in[1]=v0.y; in[2]=v0.z; in[3]=v0.w;
                    in[4]=v1.x; in[5]=v1.y; in[6]=v1.z; in[7]=v1.w;
                    in[8]=v2.x; in[9]=v2.y; in[10]=v2.z; in[11]=v2.w;
                    in[12]=v3.x; in[13]=v3.y; in[14]=v3.z; in[15]=v3.w;
                } else {
                    #pragma unroll
                    for (int i = 0; i < 16; i++) in[i] = 0.f;
                }
                u64 cw[5];
                #pragma unroll
                for (int d = 0; d < 5; d++)
                    cw[d] = (iy6 < 5)
                        ? *reinterpret_cast<const u64*>(&w1t[(iy6*5 + d)*8 + c0]) : 0ull;
                #pragma unroll
                for (int d = 0; d < 5; d++) {
                    #pragma unroll
                    for (int j = 0; j < 8; j++) {
                        u64 x2 = dup2(in[j + d + 2]);
                        fma2(A0[j], x2, cw[d]);
                        fma2(A1[j], x2, pw[d]);
                    }
                }
                #pragma unroll
                for (int d = 0; d < 5; d++) pw[d] = cw[d];
            }
            float4 o0, o1;
            {
                float2 q0[8], q1[8];
                #pragma unroll
                for (int j = 0; j < 8; j++) { q0[j] = upk(A0[j]); q1[j] = upk(A1[j]); }
                o0.x = relu(fmaxf(fmaxf(q0[0].x,q0[1].x), fmaxf(q1[0].x,q1[1].x)));
                o0.y = relu(fmaxf(fmaxf(q0[2].x,q0[3].x), fmaxf(q1[2].x,q1[3].x)));
                o0.z = relu(fmaxf(fmaxf(q0[4].x,q0[5].x), fmaxf(q1[4].x,q1[5].x)));
                o0.w = relu(fmaxf(fmaxf(q0[6].x,q0[7].x), fmaxf(q1[6].x,q1[7].x)));
                o1.x = relu(fmaxf(fmaxf(q0[0].y,q0[1].y), fmaxf(q1[0].y,q1[1].y)));
                o1.y = relu(fmaxf(fmaxf(q0[2].y,q0[3].y), fmaxf(q1[2].y,q1[3].y)));
                o1.z = relu(fmaxf(fmaxf(q0[4].y,q0[5].y), fmaxf(q1[4].y,q1[5].y)));
                o1.w = relu(fmaxf(fmaxf(q0[6].y,q0[7].y), fmaxf(q1[6].y,q1[7].y)));
            }
            int pr = prow(py);
            *reinterpret_cast<float4*>(&p1[c0*P1PLANE     + pr*P1S + 4 + xg*4]) = o0;
            *reinterpret_cast<float4*>(&p1[(c0+1)*P1PLANE + pr*P1S + 4 + xg*4]) = o1;
        }
        __syncthreads();

        // ---- conv2 (8->16,5x5,pad2)+relu+pool2 ; py fastest, perm rows ----
        {
            int py = t & 15, xg = (t >> 4) & 3, cp = t >> 6;
            int Xc = xg * 8, Y = py * 2;
            int c0 = cp * 2;
            u64 bias2 = *reinterpret_cast<const u64*>(&c2b[l*16 + c0]);
            u64 A0[8], A1[8];
            #pragma unroll
            for (int j = 0; j < 8; j++) { A0[j] = bias2; A1[j] = bias2; }
            #pragma unroll 1
            for (int ci = 0; ci < 8; ci++) {
                const float* pch = p1 + ci*P1PLANE;
                const float* wch = w2t + ci*400;
                u64 pw[5];
                #pragma unroll
                for (int d = 0; d < 5; d++) pw[d] = 0;
                #pragma unroll
                for (int iy6 = 0; iy6 < 6; iy6++) {
                    int iy = Y - 2 + iy6;
                    float in[16];
                    if ((unsigned)iy < 32u) {
                        const float* rp = pch + prow(iy)*P1S + Xc;
                        float4 v0 = *reinterpret_cast<const float4*>(rp);
                        float4 v1 = *reinterpret_cast<const float4*>(rp + 4);
                        float4 v2 = *reinterpret_cast<const float4*>(rp + 8);
                        float4 v3 = *reinterpret_cast<const float4*>(rp + 12);
                        in[0]=v0.x; in[1]=v0.y; in[2]=v0.z; in[3]=v0.w;
                        in[4]=v1.x; in[5]=v1.y; in[6]=v1.z; in[7]=v1.w;
                        in[8]=v2.x; in[9]=v2.y; in[10]=v2.z; in[11]=v2.w;
                        in[12]=v3.x; in[13]=v3.y; in[14]=v3.z; in[15]=v3.w;
                    } else {
                        #pragma unroll
                        for (int i = 0; i < 16; i++) in[i] = 0.f;
                    }
                    u64 cw[5];
                    #pragma unroll
                    for (int d = 0; d < 5; d++)
                        cw[d] = (iy6 < 5)
                            ? *reinterpret_cast<const u64*>(&wch[(iy6*5 + d)*16 + c0]) : 0ull;
                    #pragma unroll
                    for (int d = 0; d < 5; d++) {
                        #pragma unroll
                        for (int j = 0; j < 8; j++) {
                            u64 x2 = dup2(in[j + d + 2]);
                            fma2(A0[j], x2, cw[d]);
                            fma2(A1[j], x2, pw[d]);
                        }
                    }
                    #pragma unroll
                    for (int d = 0; d < 5; d++) pw[d] = cw[d];
                }
            }
            float4 o0, o1;
            {
                float2 q0[8], q1[8];
                #pragma unroll
                for (int j = 0; j < 8; j++) { q0[j] = upk(A0[j]); q1[j] = upk(A1[j]); }
                o0.x = relu(fmaxf(fmaxf(q0[0].x,q0[1].x), fmaxf(q1[0].x,q1[1].x)));
                o0.y = relu(fmaxf(fmaxf(q0[2].x,q0[3].x), fmaxf(q1[2].x,q1[3].x)));
                o0.z = relu(fmaxf(fmaxf(q0[4].x,q0[5].x), fmaxf(q1[4].x,q1[5].x)));
                o0.w = relu(fmaxf(fmaxf(q0[6].x,q0[7].x), fmaxf(q1[6].x,q1[7].x)));
                o1.x = relu(fmaxf(fmaxf(q0[0].y,q0[1].y), fmaxf(q1[0].y,q1[1].y)));
                o1.y = relu(fmaxf(fmaxf(q0[2].y,q0[3].y), fmaxf(q1[2].y,q1[3].y)));
                o1.z = relu(fmaxf(fmaxf(q0[4].y,q0[5].y), fmaxf(q1[4].y,q1[5].y)));
                o1.w = relu(fmaxf(fmaxf(q0[6].y,q0[7].y), fmaxf(q1[6].y,q1[7].y)));
            }
            *reinterpret_cast<float4*>(
                &g_feat[b*FEAT_DIM + ((l*16 + c0)*16 + py)*16 + xg*4])     = o0;
            *reinterpret_cast<float4*>(
                &g_feat[b*FEAT_DIM + ((l*16 + c0 + 1)*16 + py)*16 + xg*4]) = o1;
        }
        __syncthreads();
    }
}

// ---- partial = feat @ lin_w (K slice) : 128x64 tiles, 4 slices, 2 CTA/SM ----
__global__ __launch_bounds__(256, 2)
void lin_kernel(const float* __restrict__ Wl)
{
    __shared__ __align__(16) float As[128][36];  // 18432 B
    __shared__ __align__(16) float Bs[32][72];   // 9216 B
    const int blk   = blockIdx.x & 63;
    const int slice = blockIdx.x >> 6;           // 0..3
    const int bn = blk & 7;
    const int bm = blk >> 3;                     // 0..7
    const int t  = threadIdx.x;
    const int tyg = t & 31;                      // i rows: tyg + 32m
    const int txg = t >> 5;                      // j0 = txg*8
    const int j0 = txg * 8;
    const int rowBase = bm * 128, colBase = bn * 64;
    const int kBase = slice * KS4;
    float* out = g_hidp[slice];

    u64 acc2[4][4] = {};                         // [i-row m][j-pair]
    for (int kt = kBase; kt < kBase + KS4; kt += 32) {
        #pragma unroll
        for (int r = 0; r < 16; r++) {
            int idx = t + r*256;
            int row = idx >> 5, kk = idx & 31;
            As[row][kk] = g_feat[(rowBase + row)*FEAT_DIM + kt + kk];
        }
        #pragma unroll
        for (int r = 0; r < 8; r++) {
            int idx = t + r*256;
            int row = idx >> 6, col = idx & 63;
            Bs[row][col] = Wl[(kt + row)*512 + colBase + col];
        }
        __syncthreads();
        #pragma unroll
        for (int k = 0; k < 32; k += 4) {
            float4 av[4];
            #pragma unroll
            for (int m = 0; m < 4; m++)
                av[m] = *reinterpret_cast<const float4*>(&As[tyg + 32*m][k]);
            #pragma unroll
            for (int kk = 0; kk < 4; kk++) {
                ulonglong2 bvA = *reinterpret_cast<const ulonglong2*>(&Bs[k + kk][j0]);
                ulonglong2 bvB = *reinterpret_cast<const ulonglong2*>(&Bs[k + kk][j0 + 4]);
                #pragma unroll
                for (int m = 0; m < 4; m++) {
                    float a = kk == 0 ? av[m].x : kk == 1 ? av[m].y : kk == 2 ? av[m].z : av[m].w;
                    u64 a2 = dup2(a);
                    fma2(acc2[m][0], a2, bvA.x);
                    fma2(acc2[m][1], a2, bvA.y);
                    fma2(acc2[m][2], a2, bvB.x);
                    fma2(acc2[m][3], a2, bvB.y);
                }
            }
        }
        __syncthreads();
    }
    #pragma unroll
    for (int m = 0; m < 4; m++) {
        ulonglong2 sA; sA.x = acc2[m][0]; sA.y = acc2[m][1];
        ulonglong2 sB; sB.x = acc2[m][2]; sB.y = acc2[m][3];
        float* op = &out[(rowBase + tyg + 32*m)*512 + colBase + j0];
        *reinterpret_cast<ulonglong2*>(op)     = sA;
        *reinterpret_cast<ulonglong2*>(op + 4) = sB;
    }
}

// ---- out = relu(sum partials + lin_b) @ score_w + score_b ----
__global__ __launch_bounds__(256)
void score_kernel(const float* __restrict__ bl,
                  const float* __restrict__ sw, const float* __restrict__ sb,
                  float* __restrict__ out)
{
    int gw   = (blockIdx.x * blockDim.x + threadIdx.x) >> 5;
    int lane = threadIdx.x & 31;
    if (gw >= NB) return;
    const float* h0 = g_hidp[0] + gw * 512;
    const float* h1 = g_hidp[1] + gw * 512;
    const float* h2 = g_hidp[2] + gw * 512;
    const float* h3 = g_hidp[3] + gw * 512;
    float s = 0.f;
    #pragma unroll
    for (int j = lane; j < 512; j += 32)
        s += relu(h0[j] + h1[j] + h2[j] + h3[j] + bl[j]) * sw[j];
    #pragma unroll
    for (int o = 16; o > 0; o >>= 1) s += __shfl_xor_sync(0xFFFFFFFFu, s, o);
    if (lane == 0) out[gw] = s + sb[0];
}

extern "C" void kernel_launch(void* const* d_in, const int* in_sizes, int n_in,
                              void* d_out, int out_size)
{
    const float* x_q  = (const float*)d_in[0];
    const float* x_c  = (const float*)d_in[1];
    const float* w0   = (const float*)d_in[2];
    const float* b0   = (const float*)d_in[3];
    const float* w1   = (const float*)d_in[4];
    const float* b1   = (const float*)d_in[5];
    const float* w2   = (const float*)d_in[6];
    const float* b2   = (const float*)d_in[7];
    const float* c1w  = (const float*)d_in[8];
    const float* c1b  = (const float*)d_in[9];
    const float* c2w  = (const float*)d_in[10];
    const float* c2b  = (const float*)d_in[11];
    const float* linw = (const float*)d_in[12];
    const float* linb = (const float*)d_in[13];
    const float* scw  = (const float*)d_in[14];
    const float* scb  = (const float*)d_in[15];
    const int*   eiq  = (const int*)d_in[16];
    const int*   eic  = (const int*)d_in[17];

    cudaFuncSetAttribute(fused_kernel, cudaFuncAttributeMaxDynamicSharedMemorySize, SMEM_BYTES);

    fused_kernel<<<NB, 512, SMEM_BYTES>>>(x_q, x_c, w0, b0, w1, b1, w2, b2,
                                          c1w, c1b, c2w, c2b, eiq, eic);
    lin_kernel<<<256, 256>>>(linw);
    score_kernel<<<128, 256>>>(linb, scw, scb, (float*)d_out);
}